// round 1
// baseline (speedup 1.0000x reference)
#include <cuda_runtime.h>

#define BB    2
#define CC    256
#define HW    2304
#define HEADS 8
#define DK    32
#define CR    32
#define NCH   (BB*CC*HW)

// ---------------- scratch (device globals; no allocation) ----------------
__device__ float g_q[NCH];
__device__ float g_k[NCH];
__device__ float g_v[NCH];
__device__ float g_w[NCH];              // wf projection
__device__ float g_m[BB*CR*HW];
__device__ float g_n[BB*CR*HW];
__device__ float g_tsa[NCH];
__device__ float g_gsa[NCH];
__device__ float g_pa[(size_t)BB*HW*HW]; // 42.5 MB

// ---------------- fast exp on the FMA pipe (no MUFU) ----------------
__device__ __forceinline__ float fexp(float x) {
    float t = x * 1.4426950408889634f;      // log2(e)
    t = fmaxf(t, -126.0f);
    float r = t + 12582912.0f;              // round to nearest int (2^23*1.5)
    int   ii = __float_as_int(r) - 0x4B400000;
    float fi = r - 12582912.0f;
    float f  = t - fi;                      // f in [-0.5, 0.5]
    float p  = 1.3333558e-3f;
    p = fmaf(p, f, 9.6181291e-3f);
    p = fmaf(p, f, 5.5504109e-2f);
    p = fmaf(p, f, 2.4022651e-1f);
    p = fmaf(p, f, 6.9314718e-1f);
    p = fmaf(p, f, 1.0f);
    return __int_as_float(__float_as_int(p) + (ii << 23));
}

// ---------------- generic 1x1-conv GEMM: out[b,o,j] = W[o,:]·x[b,:,j] + bias[o] ----
// grid: (B*HW/64, ceil(Co/64)), block 256
__global__ void __launch_bounds__(256) proj_gemm(
    const float* __restrict__ W, const float* __restrict__ bias,
    const float* __restrict__ x, float* __restrict__ out, int Co)
{
    __shared__ float As[16][64];   // As[k][o]
    __shared__ float Bs[16][64];   // Bs[k][j]
    int jt  = blockIdx.x;
    int o0  = blockIdx.y * 64;
    int b   = (jt * 64) / HW;
    int hw0 = (jt * 64) % HW;
    const float* xb = x + (size_t)b * CC * HW + hw0;
    int tid = threadIdx.x;
    int tx = tid & 15, ty = tid >> 4;
    float acc[4][4];
#pragma unroll
    for (int i = 0; i < 4; i++)
#pragma unroll
        for (int j = 0; j < 4; j++) acc[i][j] = 0.f;

    int lo  = tid >> 2;            // W row in tile
    int lk4 = (tid & 3) * 4;       // k quad
    int bk  = tid >> 4;            // x k row
    int bj4 = (tid & 15) * 4;      // x col quad

    for (int k0 = 0; k0 < CC; k0 += 16) {
        float4 wv = make_float4(0.f, 0.f, 0.f, 0.f);
        if (o0 + lo < Co)
            wv = *(const float4*)(W + (size_t)(o0 + lo) * CC + k0 + lk4);
        As[lk4 + 0][lo] = wv.x; As[lk4 + 1][lo] = wv.y;
        As[lk4 + 2][lo] = wv.z; As[lk4 + 3][lo] = wv.w;
        float4 xv = *(const float4*)(xb + (size_t)(k0 + bk) * HW + bj4);
        *(float4*)&Bs[bk][bj4] = xv;
        __syncthreads();
#pragma unroll
        for (int k = 0; k < 16; k++) {
            float4 a  = *(float4*)&As[k][ty * 4];
            float4 bb = *(float4*)&Bs[k][tx * 4];
            float av[4] = {a.x, a.y, a.z, a.w};
            float bv[4] = {bb.x, bb.y, bb.z, bb.w};
#pragma unroll
            for (int i = 0; i < 4; i++)
#pragma unroll
                for (int j = 0; j < 4; j++)
                    acc[i][j] = fmaf(av[i], bv[j], acc[i][j]);
        }
        __syncthreads();
    }
#pragma unroll
    for (int i = 0; i < 4; i++) {
        int o = o0 + ty * 4 + i;
        if (o < Co) {
            float bsv = bias[o];
            float4 ov = make_float4(acc[i][0] + bsv, acc[i][1] + bsv,
                                    acc[i][2] + bsv, acc[i][3] + bsv);
            *(float4*)(out + (size_t)b * Co * HW + (size_t)o * HW + hw0 + tx * 4) = ov;
        }
    }
}

// ---------------- flash TSA: per (b,h), 64 q-rows per block ----------------
// grid: (HW/64=36, B*HEADS=16), block 256
__global__ void __launch_bounds__(256) flash_tsa()
{
    __shared__ float Qs[32][64];   // Qs[d][i], pre-scaled
    __shared__ float Ks[32][64];   // Ks[d][j]
    __shared__ float Vs[64][33];   // Vs[j][d]
    __shared__ float Ps[64][65];   // Ps[j][i]
    int bh = blockIdx.y;
    int b = bh >> 3, h = bh & 7;
    int i0 = blockIdx.x * 64;
    const float* qb = g_q + (size_t)b * CC * HW + (size_t)(h * DK) * HW;
    const float* kb = g_k + (size_t)b * CC * HW + (size_t)(h * DK) * HW;
    const float* vb = g_v + (size_t)b * CC * HW + (size_t)(h * DK) * HW;
    int tid = threadIdx.x;
    int tx = tid & 15, ty = tid >> 4;
    const float scale = 0.17677669529663687f; // 1/sqrt(32)

    for (int e = tid; e < 2048; e += 256) {
        int d = e >> 6, i = e & 63;
        Qs[d][i] = qb[(size_t)d * HW + i0 + i] * scale;
    }
    float m_[4], l_[4], o_[4][2];
#pragma unroll
    for (int r = 0; r < 4; r++) { m_[r] = -1e30f; l_[r] = 0.f; o_[r][0] = 0.f; o_[r][1] = 0.f; }

    for (int kt = 0; kt < 36; kt++) {
        int j0 = kt * 64;
        __syncthreads();                       // prev PV done before K/V/P reuse
        for (int e = tid; e < 2048; e += 256) {
            int d = e >> 6, j = e & 63;
            float kvv = kb[(size_t)d * HW + j0 + j];
            float vvv = vb[(size_t)d * HW + j0 + j];
            Ks[d][j] = kvv;
            Vs[j][d] = vvv;
        }
        __syncthreads();
        float s[4][4];
#pragma unroll
        for (int i = 0; i < 4; i++)
#pragma unroll
            for (int j = 0; j < 4; j++) s[i][j] = 0.f;
#pragma unroll
        for (int d = 0; d < 32; d++) {
            float4 a  = *(float4*)&Qs[d][ty * 4];
            float4 kk = *(float4*)&Ks[d][tx * 4];
            float av[4] = {a.x, a.y, a.z, a.w};
            float kv[4] = {kk.x, kk.y, kk.z, kk.w};
#pragma unroll
            for (int i = 0; i < 4; i++)
#pragma unroll
                for (int j = 0; j < 4; j++)
                    s[i][j] = fmaf(av[i], kv[j], s[i][j]);
        }
        // online softmax, per row (shared across the 16 tx lanes of this ty)
#pragma unroll
        for (int r = 0; r < 4; r++) {
            float rm = fmaxf(fmaxf(s[r][0], s[r][1]), fmaxf(s[r][2], s[r][3]));
#pragma unroll
            for (int off = 8; off; off >>= 1)
                rm = fmaxf(rm, __shfl_xor_sync(0xffffffffu, rm, off));
            float mn = fmaxf(m_[r], rm);
            float corr = fexp(m_[r] - mn);
            float ps = 0.f;
#pragma unroll
            for (int j = 0; j < 4; j++) {
                float p = fexp(s[r][j] - mn);
                s[r][j] = p;
                ps += p;
            }
#pragma unroll
            for (int off = 8; off; off >>= 1)
                ps += __shfl_xor_sync(0xffffffffu, ps, off);
            l_[r] = l_[r] * corr + ps;
            m_[r] = mn;
            o_[r][0] *= corr; o_[r][1] *= corr;
#pragma unroll
            for (int j = 0; j < 4; j++)
                Ps[tx * 4 + j][ty * 4 + r] = s[r][j];
        }
        __syncthreads();
        int ib = ty * 4;
        int d0 = tx * 2;
#pragma unroll 8
        for (int j = 0; j < 64; j++) {
            float v0 = Vs[j][d0], v1 = Vs[j][d0 + 1];
#pragma unroll
            for (int r = 0; r < 4; r++) {
                float p = Ps[j][ib + r];
                o_[r][0] = fmaf(p, v0, o_[r][0]);
                o_[r][1] = fmaf(p, v1, o_[r][1]);
            }
        }
    }
    float* ob = g_tsa + (size_t)b * CC * HW + (size_t)(h * DK) * HW;
#pragma unroll
    for (int r = 0; r < 4; r++) {
        float inv = 1.f / l_[r];
        int i = i0 + ty * 4 + r;
        ob[(size_t)(tx * 2 + 0) * HW + i] = o_[r][0] * inv;
        ob[(size_t)(tx * 2 + 1) * HW + i] = o_[r][1] * inv;
    }
}

// ---------------- GSA raw scores: pa[b,n,m] = m[b,:,n]·n[b,:,m] ----------------
// grid: (36, 36, B), block 256
__global__ void __launch_bounds__(256) pa_gemm()
{
    __shared__ float Ms[32][64];
    __shared__ float Ns[32][64];
    int b  = blockIdx.z;
    int i0 = blockIdx.x * 64;   // n
    int j0 = blockIdx.y * 64;   // m
    const float* mb = g_m + (size_t)b * CR * HW;
    const float* nb = g_n + (size_t)b * CR * HW;
    int tid = threadIdx.x;
    int tx = tid & 15, ty = tid >> 4;
    for (int e = tid; e < 2048; e += 256) {
        int c = e >> 6, i = e & 63;
        Ms[c][i] = mb[(size_t)c * HW + i0 + i];
        Ns[c][i] = nb[(size_t)c * HW + j0 + i];
    }
    __syncthreads();
    float acc[4][4];
#pragma unroll
    for (int i = 0; i < 4; i++)
#pragma unroll
        for (int j = 0; j < 4; j++) acc[i][j] = 0.f;
#pragma unroll
    for (int c = 0; c < 32; c++) {
        float4 a  = *(float4*)&Ms[c][ty * 4];
        float4 nn = *(float4*)&Ns[c][tx * 4];
        float av[4] = {a.x, a.y, a.z, a.w};
        float nv[4] = {nn.x, nn.y, nn.z, nn.w};
#pragma unroll
        for (int i = 0; i < 4; i++)
#pragma unroll
            for (int j = 0; j < 4; j++)
                acc[i][j] = fmaf(av[i], nv[j], acc[i][j]);
    }
    float* pb = g_pa + (size_t)b * HW * HW;
#pragma unroll
    for (int i = 0; i < 4; i++) {
        float4 ov = make_float4(acc[i][0], acc[i][1], acc[i][2], acc[i][3]);
        *(float4*)(pb + (size_t)(i0 + ty * 4 + i) * HW + j0 + tx * 4) = ov;
    }
}

// ---------------- row softmax over pa (in place) ----------------
// grid: B*HW = 4608, block 256
__global__ void __launch_bounds__(256) softmax_rows()
{
    __shared__ float red[8];
    size_t row = blockIdx.x;
    float* p = g_pa + row * HW;
    int tid = threadIdx.x;
    float v[9];
    float mx = -1e30f;
#pragma unroll
    for (int e = 0; e < 9; e++) { v[e] = p[tid + 256 * e]; mx = fmaxf(mx, v[e]); }
#pragma unroll
    for (int off = 16; off; off >>= 1)
        mx = fmaxf(mx, __shfl_xor_sync(0xffffffffu, mx, off));
    if ((tid & 31) == 0) red[tid >> 5] = mx;
    __syncthreads();
    float m8 = red[0];
#pragma unroll
    for (int i = 1; i < 8; i++) m8 = fmaxf(m8, red[i]);
    float s = 0.f;
#pragma unroll
    for (int e = 0; e < 9; e++) { v[e] = fexp(v[e] - m8); s += v[e]; }
#pragma unroll
    for (int off = 16; off; off >>= 1)
        s += __shfl_xor_sync(0xffffffffu, s, off);
    __syncthreads();
    if ((tid & 31) == 0) red[tid >> 5] = s;
    __syncthreads();
    float s8 = 0.f;
#pragma unroll
    for (int i = 0; i < 8; i++) s8 += red[i];
    float inv = 1.f / s8;
#pragma unroll
    for (int e = 0; e < 9; e++) p[tid + 256 * e] = v[e] * inv;
}

// ---------------- gsa[b,c,n] = sum_m wf[b,c,m] * pa[b,n,m] ----------------
// grid: (36, 4, B), block 256
__global__ void __launch_bounds__(256) gsa_gemm()
{
    __shared__ float As[16][64];   // As[k][c]
    __shared__ float Bs[16][64];   // Bs[k][n]
    int b  = blockIdx.z;
    int i0 = blockIdx.x * 64;      // n
    int c0 = blockIdx.y * 64;      // c
    const float* wfb = g_w  + (size_t)b * CC * HW;
    const float* pab = g_pa + (size_t)b * HW * HW;
    int tid = threadIdx.x;
    int tx = tid & 15, ty = tid >> 4;
    int r64 = tid >> 2;
    int k4  = (tid & 3) * 4;
    float acc[4][4];
#pragma unroll
    for (int i = 0; i < 4; i++)
#pragma unroll
        for (int j = 0; j < 4; j++) acc[i][j] = 0.f;

    for (int m0 = 0; m0 < HW; m0 += 16) {
        float4 wv = *(const float4*)(wfb + (size_t)(c0 + r64) * HW + m0 + k4);
        As[k4 + 0][r64] = wv.x; As[k4 + 1][r64] = wv.y;
        As[k4 + 2][r64] = wv.z; As[k4 + 3][r64] = wv.w;
        float4 pv = *(const float4*)(pab + (size_t)(i0 + r64) * HW + m0 + k4);
        Bs[k4 + 0][r64] = pv.x; Bs[k4 + 1][r64] = pv.y;
        Bs[k4 + 2][r64] = pv.z; Bs[k4 + 3][r64] = pv.w;
        __syncthreads();
#pragma unroll
        for (int k = 0; k < 16; k++) {
            float4 a  = *(float4*)&As[k][ty * 4];
            float4 bb = *(float4*)&Bs[k][tx * 4];
            float av[4] = {a.x, a.y, a.z, a.w};
            float bv[4] = {bb.x, bb.y, bb.z, bb.w};
#pragma unroll
            for (int i = 0; i < 4; i++)
#pragma unroll
                for (int j = 0; j < 4; j++)
                    acc[i][j] = fmaf(av[i], bv[j], acc[i][j]);
        }
        __syncthreads();
    }
    float* ob = g_gsa + (size_t)b * CC * HW;
#pragma unroll
    for (int i = 0; i < 4; i++) {
        float4 ov = make_float4(acc[i][0], acc[i][1], acc[i][2], acc[i][3]);
        *(float4*)(ob + (size_t)(c0 + ty * 4 + i) * HW + i0 + tx * 4) = ov;
    }
}

// ---------------- final: out = gt*tsa + gg*(wo@gsa + bo) + x ----------------
// grid: (72, 4), block 256
__global__ void __launch_bounds__(256) final_gemm(
    const float* __restrict__ wo, const float* __restrict__ bo,
    const float* __restrict__ x,
    const float* __restrict__ gt_p, const float* __restrict__ gg_p,
    float* __restrict__ out)
{
    __shared__ float As[16][64];
    __shared__ float Bs[16][64];
    int jt  = blockIdx.x;
    int c0  = blockIdx.y * 64;
    int b   = (jt * 64) / HW;
    int hw0 = (jt * 64) % HW;
    const float* gb = g_gsa + (size_t)b * CC * HW + hw0;
    int tid = threadIdx.x;
    int tx = tid & 15, ty = tid >> 4;
    float acc[4][4];
#pragma unroll
    for (int i = 0; i < 4; i++)
#pragma unroll
        for (int j = 0; j < 4; j++) acc[i][j] = 0.f;

    int lo  = tid >> 2;
    int lk4 = (tid & 3) * 4;
    int bk  = tid >> 4;
    int bj4 = (tid & 15) * 4;

    for (int k0 = 0; k0 < CC; k0 += 16) {
        float4 wv = *(const float4*)(wo + (size_t)(c0 + lo) * CC + k0 + lk4);
        As[lk4 + 0][lo] = wv.x; As[lk4 + 1][lo] = wv.y;
        As[lk4 + 2][lo] = wv.z; As[lk4 + 3][lo] = wv.w;
        float4 xv = *(const float4*)(gb + (size_t)(k0 + bk) * HW + bj4);
        *(float4*)&Bs[bk][bj4] = xv;
        __syncthreads();
#pragma unroll
        for (int k = 0; k < 16; k++) {
            float4 a  = *(float4*)&As[k][ty * 4];
            float4 bb = *(float4*)&Bs[k][tx * 4];
            float av[4] = {a.x, a.y, a.z, a.w};
            float bv[4] = {bb.x, bb.y, bb.z, bb.w};
#pragma unroll
            for (int i = 0; i < 4; i++)
#pragma unroll
                for (int j = 0; j < 4; j++)
                    acc[i][j] = fmaf(av[i], bv[j], acc[i][j]);
        }
        __syncthreads();
    }
    float gt = gt_p[0], gg = gg_p[0];
#pragma unroll
    for (int i = 0; i < 4; i++) {
        int c = c0 + ty * 4 + i;
        float bv = bo[c];
        size_t base = (size_t)b * CC * HW + (size_t)c * HW + hw0 + tx * 4;
        float4 xv = *(const float4*)(x + base);
        float4 tv = *(const float4*)(g_tsa + base);
        float4 ov;
        ov.x = gt * tv.x + gg * (acc[i][0] + bv) + xv.x;
        ov.y = gt * tv.y + gg * (acc[i][1] + bv) + xv.y;
        ov.z = gt * tv.z + gg * (acc[i][2] + bv) + xv.z;
        ov.w = gt * tv.w + gg * (acc[i][3] + bv) + xv.w;
        *(float4*)(out + base) = ov;
    }
}

// ---------------- launch ----------------
extern "C" void kernel_launch(void* const* d_in, const int* in_sizes, int n_in,
                              void* d_out, int out_size)
{
    const float* x   = (const float*)d_in[0];
    const float* wq  = (const float*)d_in[1];
    const float* bq  = (const float*)d_in[2];
    const float* wk  = (const float*)d_in[3];
    const float* bk  = (const float*)d_in[4];
    const float* wv  = (const float*)d_in[5];
    const float* bv  = (const float*)d_in[6];
    const float* wm  = (const float*)d_in[7];
    const float* bm  = (const float*)d_in[8];
    const float* wn  = (const float*)d_in[9];
    const float* bn  = (const float*)d_in[10];
    const float* ww  = (const float*)d_in[11];
    const float* bw  = (const float*)d_in[12];
    const float* wo  = (const float*)d_in[13];
    const float* bo  = (const float*)d_in[14];
    const float* gts = (const float*)d_in[15];
    const float* ggs = (const float*)d_in[16];
    float* out = (float*)d_out;

    float *pq, *pk, *pv, *pw, *pm, *pn;
    cudaGetSymbolAddress((void**)&pq, g_q);
    cudaGetSymbolAddress((void**)&pk, g_k);
    cudaGetSymbolAddress((void**)&pv, g_v);
    cudaGetSymbolAddress((void**)&pw, g_w);
    cudaGetSymbolAddress((void**)&pm, g_m);
    cudaGetSymbolAddress((void**)&pn, g_n);

    dim3 blk(256);
    dim3 gproj(BB * HW / 64, CC / 64);      // (72, 4)
    dim3 gprojr(BB * HW / 64, 1);           // (72, 1)

    proj_gemm<<<gproj,  blk>>>(wq, bq, x, pq, CC);
    proj_gemm<<<gproj,  blk>>>(wk, bk, x, pk, CC);
    proj_gemm<<<gproj,  blk>>>(wv, bv, x, pv, CC);
    proj_gemm<<<gproj,  blk>>>(ww, bw, x, pw, CC);
    proj_gemm<<<gprojr, blk>>>(wm, bm, x, pm, CR);
    proj_gemm<<<gprojr, blk>>>(wn, bn, x, pn, CR);

    flash_tsa<<<dim3(HW / 64, BB * HEADS), blk>>>();          // (36, 16)

    pa_gemm<<<dim3(HW / 64, HW / 64, BB), blk>>>();           // (36, 36, 2)
    softmax_rows<<<BB * HW, blk>>>();                          // 4608 rows
    gsa_gemm<<<dim3(HW / 64, CC / 64, BB), blk>>>();          // (36, 4, 2)

    final_gemm<<<dim3(BB * HW / 64, CC / 64), blk>>>(wo, bo, x, gts, ggs, out);
}

// round 3
// speedup vs baseline: 1.7848x; 1.7848x over previous
#include <cuda_runtime.h>
#include <cuda_bf16.h>
#include <cstdint>

#define BB    2
#define CC    256
#define HW    2304
#define HEADS 8
#define DK    32
#define CR    32
#define NCH   (BB*CC*HW)

// ---------------- scratch (device globals; no allocation) ----------------
__device__ float g_q[NCH];
__device__ float g_k[NCH];
__device__ float g_v[NCH];
__device__ float g_w[NCH];              // wf projection
__device__ float g_m[BB*CR*HW];
__device__ float g_n[BB*CR*HW];
__device__ float g_tsa[NCH];
__device__ float g_gsa[NCH];
__device__ float g_pa[(size_t)BB*HW*HW]; // 42.5 MB
__device__ __nv_bfloat16 g_qh[NCH];     // [bh][token][d], pre-scaled by 1/sqrt(dk)
__device__ __nv_bfloat16 g_kh[NCH];     // [bh][token][d]
__device__ __nv_bfloat16 g_vh[NCH];     // [bh][d][token]

// ---------------- fast exp on the FMA pipe (no MUFU) ----------------
__device__ __forceinline__ float fexp(float x) {
    float t = x * 1.4426950408889634f;
    t = fmaxf(t, -126.0f);
    float r = t + 12582912.0f;
    int   ii = __float_as_int(r) - 0x4B400000;
    float fi = r - 12582912.0f;
    float f  = t - fi;
    float p  = 1.3333558e-3f;
    p = fmaf(p, f, 9.6181291e-3f);
    p = fmaf(p, f, 5.5504109e-2f);
    p = fmaf(p, f, 2.4022651e-1f);
    p = fmaf(p, f, 6.9314718e-1f);
    p = fmaf(p, f, 1.0f);
    return __int_as_float(__float_as_int(p) + (ii << 23));
}

// ---------------- mma.sync helper (sm_80-class bf16 tensor core) ---------
__device__ __forceinline__ void mma16816(float* c, const uint32_t* a, uint32_t b0, uint32_t b1) {
    asm volatile(
        "mma.sync.aligned.m16n8k16.row.col.f32.bf16.bf16.f32 "
        "{%0,%1,%2,%3}, {%4,%5,%6,%7}, {%8,%9}, {%0,%1,%2,%3};"
        : "+f"(c[0]), "+f"(c[1]), "+f"(c[2]), "+f"(c[3])
        : "r"(a[0]), "r"(a[1]), "r"(a[2]), "r"(a[3]), "r"(b0), "r"(b1));
}
__device__ __forceinline__ uint32_t pack_bf16x2(float hi, float lo) {
    uint32_t w;
    asm("cvt.rn.satfinite.bf16x2.f32 %0, %1, %2;" : "=r"(w) : "f"(hi), "f"(lo));
    return w;
}

// ---------------- generic 1x1-conv GEMM ----------------
__global__ void __launch_bounds__(256) proj_gemm(
    const float* __restrict__ W, const float* __restrict__ bias,
    const float* __restrict__ x, float* __restrict__ out, int Co)
{
    __shared__ float As[16][64];
    __shared__ float Bs[16][64];
    int jt  = blockIdx.x;
    int o0  = blockIdx.y * 64;
    int b   = (jt * 64) / HW;
    int hw0 = (jt * 64) % HW;
    const float* xb = x + (size_t)b * CC * HW + hw0;
    int tid = threadIdx.x;
    int tx = tid & 15, ty = tid >> 4;
    float acc[4][4];
#pragma unroll
    for (int i = 0; i < 4; i++)
#pragma unroll
        for (int j = 0; j < 4; j++) acc[i][j] = 0.f;

    int lo  = tid >> 2;
    int lk4 = (tid & 3) * 4;
    int bk  = tid >> 4;
    int bj4 = (tid & 15) * 4;

    for (int k0 = 0; k0 < CC; k0 += 16) {
        float4 wv = make_float4(0.f, 0.f, 0.f, 0.f);
        if (o0 + lo < Co)
            wv = *(const float4*)(W + (size_t)(o0 + lo) * CC + k0 + lk4);
        As[lk4 + 0][lo] = wv.x; As[lk4 + 1][lo] = wv.y;
        As[lk4 + 2][lo] = wv.z; As[lk4 + 3][lo] = wv.w;
        float4 xv = *(const float4*)(xb + (size_t)(k0 + bk) * HW + bj4);
        *(float4*)&Bs[bk][bj4] = xv;
        __syncthreads();
#pragma unroll
        for (int k = 0; k < 16; k++) {
            float4 a  = *(float4*)&As[k][ty * 4];
            float4 bb = *(float4*)&Bs[k][tx * 4];
            float av[4] = {a.x, a.y, a.z, a.w};
            float bv[4] = {bb.x, bb.y, bb.z, bb.w};
#pragma unroll
            for (int i = 0; i < 4; i++)
#pragma unroll
                for (int j = 0; j < 4; j++)
                    acc[i][j] = fmaf(av[i], bv[j], acc[i][j]);
        }
        __syncthreads();
    }
#pragma unroll
    for (int i = 0; i < 4; i++) {
        int o = o0 + ty * 4 + i;
        if (o < Co) {
            float bsv = bias[o];
            float4 ov = make_float4(acc[i][0] + bsv, acc[i][1] + bsv,
                                    acc[i][2] + bsv, acc[i][3] + bsv);
            *(float4*)(out + (size_t)b * Co * HW + (size_t)o * HW + hw0 + tx * 4) = ov;
        }
    }
}

// ---------------- converters for the tensor-core flash ----------------
// transpose [bh][d][t] fp32 -> [bh][t][d] bf16 (optional scale)
__global__ void __launch_bounds__(256) conv_qk(
    const float* __restrict__ src, __nv_bfloat16* __restrict__ dst, float scale)
{
    __shared__ float t[32][65];
    int bh = blockIdx.y;
    int t0 = blockIdx.x * 64;
    const float* s = src + (size_t)bh * 32 * HW + t0;
    int tid = threadIdx.x;
    for (int e = tid; e < 2048; e += 256) {
        int d = e >> 6, tt = e & 63;
        t[d][tt] = s[(size_t)d * HW + tt] * scale;
    }
    __syncthreads();
    int j = tid >> 2, seg = (tid & 3) * 8;
    __nv_bfloat16 tmp[8];
#pragma unroll
    for (int i = 0; i < 8; i++) tmp[i] = __float2bfloat16(t[seg + i][j]);
    *(uint4*)(dst + ((size_t)bh * HW + t0 + j) * DK + seg) = *(uint4*)tmp;
}

__global__ void __launch_bounds__(256) conv_v()
{
    size_t i = ((size_t)blockIdx.x * 256 + threadIdx.x) * 4;
    float4 v = *(const float4*)(g_v + i);
    __nv_bfloat16 t[4];
    t[0] = __float2bfloat16(v.x); t[1] = __float2bfloat16(v.y);
    t[2] = __float2bfloat16(v.z); t[3] = __float2bfloat16(v.w);
    *(uint2*)(g_vh + i) = *(uint2*)t;
}

// ---------------- FA2-style flash TSA with mma.sync bf16 ----------------
// grid (18, 16), block 256 (8 warps). Warp w: q rows [16w, 16w+16) of this
// CTA's 128-row q tile. K-tile = 128 tokens, 18 iterations.
// No running max: scores are bounded (|s| <~ 30) so exp is fp32-safe.
#define QS_STR 40    // halves per row (32 data + 8 pad) -> conflict-free frags
#define VS_STR 136   // halves per row (128 data + 8 pad)
__global__ void __launch_bounds__(256) flash_mma()
{
    __shared__ __nv_bfloat16 Qs[128 * QS_STR];  // 10240 B
    __shared__ __nv_bfloat16 Ks[128 * QS_STR];  // 10240 B
    __shared__ __nv_bfloat16 Vs[32 * VS_STR];   //  8704 B
    int tid = threadIdx.x, wid = tid >> 5, lane = tid & 31;
    int bh = blockIdx.y, i0 = blockIdx.x * 128;
    int gr = lane >> 2, gc = (lane & 3) * 2;

    const __nv_bfloat16* qsrc = g_qh + ((size_t)bh * HW + i0) * DK;
    const __nv_bfloat16* ksrc = g_kh + (size_t)bh * HW * DK;
    const __nv_bfloat16* vsrc = g_vh + (size_t)bh * DK * HW;

    // Q tile -> smem (once)
    for (int e = tid; e < 512; e += 256) {
        int r = e >> 2, c8 = (e & 3) * 8;
        *(uint4*)(Qs + r * QS_STR + c8) = *(const uint4*)(qsrc + r * DK + c8);
    }
    __syncthreads();

    // Q fragments (persistent): A-operand for m16n8k16, K dim = d (2 chunks)
    uint32_t qa[2][4];
    {
        const __nv_bfloat16* qb = Qs + (wid * 16 + gr) * QS_STR;
#pragma unroll
        for (int kc = 0; kc < 2; kc++) {
            qa[kc][0] = *(const uint32_t*)(qb + kc * 16 + gc);
            qa[kc][1] = *(const uint32_t*)(qb + 8 * QS_STR + kc * 16 + gc);
            qa[kc][2] = *(const uint32_t*)(qb + kc * 16 + gc + 8);
            qa[kc][3] = *(const uint32_t*)(qb + 8 * QS_STR + kc * 16 + gc + 8);
        }
    }

    float o[4][4];
#pragma unroll
    for (int i = 0; i < 4; i++)
#pragma unroll
        for (int j = 0; j < 4; j++) o[i][j] = 0.f;
    float l0 = 0.f, l1 = 0.f;

    for (int kt = 0; kt < 18; kt++) {
        int j0 = kt * 128;
        __syncthreads();
        for (int e = tid; e < 512; e += 256) {          // K tile [tok][d]
            int r = e >> 2, c8 = (e & 3) * 8;
            *(uint4*)(Ks + r * QS_STR + c8) = *(const uint4*)(ksrc + (size_t)(j0 + r) * DK + c8);
        }
        for (int e = tid; e < 512; e += 256) {          // V^T tile [d][tok]
            int d = e >> 4, c8 = (e & 15) * 8;
            *(uint4*)(Vs + d * VS_STR + c8) = *(const uint4*)(vsrc + (size_t)d * HW + j0 + c8);
        }
        __syncthreads();

        // S = Q K^T : 16 n8-tiles over the 128 k-tokens
        float s[16][4];
#pragma unroll
        for (int nt = 0; nt < 16; nt++) {
            s[nt][0] = 0.f; s[nt][1] = 0.f; s[nt][2] = 0.f; s[nt][3] = 0.f;
            const __nv_bfloat16* kb = Ks + (nt * 8 + gr) * QS_STR;
#pragma unroll
            for (int kc = 0; kc < 2; kc++) {
                uint32_t b0 = *(const uint32_t*)(kb + kc * 16 + gc);
                uint32_t b1 = *(const uint32_t*)(kb + kc * 16 + gc + 8);
                mma16816(s[nt], qa[kc], b0, b1);
            }
        }

        // P = exp(S); row sums; repack C-frag pairs as A-frags for PV
        uint32_t pa_[8][4];
#pragma unroll
        for (int h2 = 0; h2 < 8; h2++) {
            float e00 = __expf(s[2 * h2][0]),     e01 = __expf(s[2 * h2][1]);
            float e02 = __expf(s[2 * h2][2]),     e03 = __expf(s[2 * h2][3]);
            float f00 = __expf(s[2 * h2 + 1][0]), f01 = __expf(s[2 * h2 + 1][1]);
            float f02 = __expf(s[2 * h2 + 1][2]), f03 = __expf(s[2 * h2 + 1][3]);
            l0 += (e00 + e01) + (f00 + f01);
            l1 += (e02 + e03) + (f02 + f03);
            pa_[h2][0] = pack_bf16x2(e01, e00);
            pa_[h2][1] = pack_bf16x2(e03, e02);
            pa_[h2][2] = pack_bf16x2(f01, f00);
            pa_[h2][3] = pack_bf16x2(f03, f02);
        }

        // O += P V : 8 k-chunks of 16 tokens, 4 n8-tiles over d=32
#pragma unroll
        for (int kc2 = 0; kc2 < 8; kc2++) {
#pragma unroll
            for (int dt = 0; dt < 4; dt++) {
                const __nv_bfloat16* vb = Vs + (dt * 8 + gr) * VS_STR + kc2 * 16 + gc;
                uint32_t b0 = *(const uint32_t*)(vb);
                uint32_t b1 = *(const uint32_t*)(vb + 8);
                mma16816(o[dt], pa_[kc2], b0, b1);
            }
        }
    }

    // finalize: quad-reduce row sums (lanes of a quad share the same rows)
    l0 += __shfl_xor_sync(0xffffffffu, l0, 1);
    l0 += __shfl_xor_sync(0xffffffffu, l0, 2);
    l1 += __shfl_xor_sync(0xffffffffu, l1, 1);
    l1 += __shfl_xor_sync(0xffffffffu, l1, 2);
    float inv0 = 1.f / l0, inv1 = 1.f / l1;

    int b = bh >> 3, h = bh & 7;
    float* ob = g_tsa + ((size_t)b * CC + h * DK) * HW;
    int tok0 = i0 + wid * 16 + gr;
#pragma unroll
    for (int dt = 0; dt < 4; dt++) {
        int d = dt * 8 + gc;
        ob[(size_t)(d)     * HW + tok0]     = o[dt][0] * inv0;
        ob[(size_t)(d + 1) * HW + tok0]     = o[dt][1] * inv0;
        ob[(size_t)(d)     * HW + tok0 + 8] = o[dt][2] * inv1;
        ob[(size_t)(d + 1) * HW + tok0 + 8] = o[dt][3] * inv1;
    }
}

// ---------------- GSA raw scores ----------------
__global__ void __launch_bounds__(256) pa_gemm()
{
    __shared__ float Ms[32][64];
    __shared__ float Ns[32][64];
    int b  = blockIdx.z;
    int i0 = blockIdx.x * 64;
    int j0 = blockIdx.y * 64;
    const float* mb_ = g_m + (size_t)b * CR * HW;
    const float* nb = g_n + (size_t)b * CR * HW;
    int tid = threadIdx.x;
    int tx = tid & 15, ty = tid >> 4;
    for (int e = tid; e < 2048; e += 256) {
        int c = e >> 6, i = e & 63;
        Ms[c][i] = mb_[(size_t)c * HW + i0 + i];
        Ns[c][i] = nb[(size_t)c * HW + j0 + i];
    }
    __syncthreads();
    float acc[4][4];
#pragma unroll
    for (int i = 0; i < 4; i++)
#pragma unroll
        for (int j = 0; j < 4; j++) acc[i][j] = 0.f;
#pragma unroll
    for (int c = 0; c < 32; c++) {
        float4 a  = *(float4*)&Ms[c][ty * 4];
        float4 nn = *(float4*)&Ns[c][tx * 4];
        float av[4] = {a.x, a.y, a.z, a.w};
        float nv[4] = {nn.x, nn.y, nn.z, nn.w};
#pragma unroll
        for (int i = 0; i < 4; i++)
#pragma unroll
            for (int j = 0; j < 4; j++)
                acc[i][j] = fmaf(av[i], nv[j], acc[i][j]);
    }
    float* pb = g_pa + (size_t)b * HW * HW;
#pragma unroll
    for (int i = 0; i < 4; i++) {
        float4 ov = make_float4(acc[i][0], acc[i][1], acc[i][2], acc[i][3]);
        *(float4*)(pb + (size_t)(i0 + ty * 4 + i) * HW + j0 + tx * 4) = ov;
    }
}

// ---------------- row softmax over pa (in place) ----------------
__global__ void __launch_bounds__(256) softmax_rows()
{
    __shared__ float red[8];
    size_t row = blockIdx.x;
    float* p = g_pa + row * HW;
    int tid = threadIdx.x;
    float v[9];
    float mx = -1e30f;
#pragma unroll
    for (int e = 0; e < 9; e++) { v[e] = p[tid + 256 * e]; mx = fmaxf(mx, v[e]); }
#pragma unroll
    for (int off = 16; off; off >>= 1)
        mx = fmaxf(mx, __shfl_xor_sync(0xffffffffu, mx, off));
    if ((tid & 31) == 0) red[tid >> 5] = mx;
    __syncthreads();
    float m8 = red[0];
#pragma unroll
    for (int i = 1; i < 8; i++) m8 = fmaxf(m8, red[i]);
    float s = 0.f;
#pragma unroll
    for (int e = 0; e < 9; e++) { v[e] = fexp(v[e] - m8); s += v[e]; }
#pragma unroll
    for (int off = 16; off; off >>= 1)
        s += __shfl_xor_sync(0xffffffffu, s, off);
    __syncthreads();
    if ((tid & 31) == 0) red[tid >> 5] = s;
    __syncthreads();
    float s8 = 0.f;
#pragma unroll
    for (int i = 0; i < 8; i++) s8 += red[i];
    float inv = 1.f / s8;
#pragma unroll
    for (int e = 0; e < 9; e++) p[tid + 256 * e] = v[e] * inv;
}

// ---------------- gsa[b,c,n] = sum_m wf[b,c,m] * pa[b,n,m] ----------------
__global__ void __launch_bounds__(256) gsa_gemm()
{
    __shared__ float As[16][64];
    __shared__ float Bs[16][64];
    int b  = blockIdx.z;
    int i0 = blockIdx.x * 64;
    int c0 = blockIdx.y * 64;
    const float* wfb = g_w  + (size_t)b * CC * HW;
    const float* pab = g_pa + (size_t)b * HW * HW;
    int tid = threadIdx.x;
    int tx = tid & 15, ty = tid >> 4;
    int r64 = tid >> 2;
    int k4  = (tid & 3) * 4;
    float acc[4][4];
#pragma unroll
    for (int i = 0; i < 4; i++)
#pragma unroll
        for (int j = 0; j < 4; j++) acc[i][j] = 0.f;

    for (int m0 = 0; m0 < HW; m0 += 16) {
        float4 wv = *(const float4*)(wfb + (size_t)(c0 + r64) * HW + m0 + k4);
        As[k4 + 0][r64] = wv.x; As[k4 + 1][r64] = wv.y;
        As[k4 + 2][r64] = wv.z; As[k4 + 3][r64] = wv.w;
        float4 pv = *(const float4*)(pab + (size_t)(i0 + r64) * HW + m0 + k4);
        Bs[k4 + 0][r64] = pv.x; Bs[k4 + 1][r64] = pv.y;
        Bs[k4 + 2][r64] = pv.z; Bs[k4 + 3][r64] = pv.w;
        __syncthreads();
#pragma unroll
        for (int k = 0; k < 16; k++) {
            float4 a  = *(float4*)&As[k][ty * 4];
            float4 bb = *(float4*)&Bs[k][tx * 4];
            float av[4] = {a.x, a.y, a.z, a.w};
            float bv[4] = {bb.x, bb.y, bb.z, bb.w};
#pragma unroll
            for (int i = 0; i < 4; i++)
#pragma unroll
                for (int j = 0; j < 4; j++)
                    acc[i][j] = fmaf(av[i], bv[j], acc[i][j]);
        }
        __syncthreads();
    }
    float* ob = g_gsa + (size_t)b * CC * HW;
#pragma unroll
    for (int i = 0; i < 4; i++) {
        float4 ov = make_float4(acc[i][0], acc[i][1], acc[i][2], acc[i][3]);
        *(float4*)(ob + (size_t)(c0 + ty * 4 + i) * HW + i0 + tx * 4) = ov;
    }
}

// ---------------- final: out = gt*tsa + gg*(wo@gsa + bo) + x ----------------
__global__ void __launch_bounds__(256) final_gemm(
    const float* __restrict__ wo, const float* __restrict__ bo,
    const float* __restrict__ x,
    const float* __restrict__ gt_p, const float* __restrict__ gg_p,
    float* __restrict__ out)
{
    __shared__ float As[16][64];
    __shared__ float Bs[16][64];
    int jt  = blockIdx.x;
    int c0  = blockIdx.y * 64;
    int b   = (jt * 64) / HW;
    int hw0 = (jt * 64) % HW;
    const float* gb = g_gsa + (size_t)b * CC * HW + hw0;
    int tid = threadIdx.x;
    int tx = tid & 15, ty = tid >> 4;
    float acc[4][4];
#pragma unroll
    for (int i = 0; i < 4; i++)
#pragma unroll
        for (int j = 0; j < 4; j++) acc[i][j] = 0.f;

    int lo  = tid >> 2;
    int lk4 = (tid & 3) * 4;
    int bk  = tid >> 4;
    int bj4 = (tid & 15) * 4;

    for (int k0 = 0; k0 < CC; k0 += 16) {
        float4 wv = *(const float4*)(wo + (size_t)(c0 + lo) * CC + k0 + lk4);
        As[lk4 + 0][lo] = wv.x; As[lk4 + 1][lo] = wv.y;
        As[lk4 + 2][lo] = wv.z; As[lk4 + 3][lo] = wv.w;
        float4 xv = *(const float4*)(gb + (size_t)(k0 + bk) * HW + bj4);
        *(float4*)&Bs[bk][bj4] = xv;
        __syncthreads();
#pragma unroll
        for (int k = 0; k < 16; k++) {
            float4 a  = *(float4*)&As[k][ty * 4];
            float4 bb = *(float4*)&Bs[k][tx * 4];
            float av[4] = {a.x, a.y, a.z, a.w};
            float bv[4] = {bb.x, bb.y, bb.z, bb.w};
#pragma unroll
            for (int i = 0; i < 4; i++)
#pragma unroll
                for (int j = 0; j < 4; j++)
                    acc[i][j] = fmaf(av[i], bv[j], acc[i][j]);
        }
        __syncthreads();
    }
    float gt = gt_p[0], gg = gg_p[0];
#pragma unroll
    for (int i = 0; i < 4; i++) {
        int c = c0 + ty * 4 + i;
        float bv = bo[c];
        size_t base = (size_t)b * CC * HW + (size_t)c * HW + hw0 + tx * 4;
        float4 xv = *(const float4*)(x + base);
        float4 tv = *(const float4*)(g_tsa + base);
        float4 ov;
        ov.x = gt * tv.x + gg * (acc[i][0] + bv) + xv.x;
        ov.y = gt * tv.y + gg * (acc[i][1] + bv) + xv.y;
        ov.z = gt * tv.z + gg * (acc[i][2] + bv) + xv.z;
        ov.w = gt * tv.w + gg * (acc[i][3] + bv) + xv.w;
        *(float4*)(out + base) = ov;
    }
}

// ---------------- launch ----------------
extern "C" void kernel_launch(void* const* d_in, const int* in_sizes, int n_in,
                              void* d_out, int out_size)
{
    const float* x   = (const float*)d_in[0];
    const float* wq  = (const float*)d_in[1];
    const float* bq  = (const float*)d_in[2];
    const float* wk  = (const float*)d_in[3];
    const float* bk  = (const float*)d_in[4];
    const float* wv  = (const float*)d_in[5];
    const float* bv  = (const float*)d_in[6];
    const float* wm  = (const float*)d_in[7];
    const float* bm  = (const float*)d_in[8];
    const float* wn  = (const float*)d_in[9];
    const float* bn  = (const float*)d_in[10];
    const float* ww  = (const float*)d_in[11];
    const float* bw  = (const float*)d_in[12];
    const float* wo  = (const float*)d_in[13];
    const float* bo  = (const float*)d_in[14];
    const float* gts = (const float*)d_in[15];
    const float* ggs = (const float*)d_in[16];
    float* out = (float*)d_out;

    float *pq, *pk, *pv, *pw, *pm, *pn;
    __nv_bfloat16 *pqh, *pkh;
    cudaGetSymbolAddress((void**)&pq, g_q);
    cudaGetSymbolAddress((void**)&pk, g_k);
    cudaGetSymbolAddress((void**)&pv, g_v);
    cudaGetSymbolAddress((void**)&pw, g_w);
    cudaGetSymbolAddress((void**)&pm, g_m);
    cudaGetSymbolAddress((void**)&pn, g_n);
    cudaGetSymbolAddress((void**)&pqh, g_qh);
    cudaGetSymbolAddress((void**)&pkh, g_kh);

    dim3 blk(256);
    dim3 gproj(BB * HW / 64, CC / 64);
    dim3 gprojr(BB * HW / 64, 1);

    proj_gemm<<<gproj,  blk>>>(wq, bq, x, pq, CC);
    proj_gemm<<<gproj,  blk>>>(wk, bk, x, pk, CC);
    proj_gemm<<<gproj,  blk>>>(wv, bv, x, pv, CC);
    proj_gemm<<<gproj,  blk>>>(ww, bw, x, pw, CC);
    proj_gemm<<<gprojr, blk>>>(wm, bm, x, pm, CR);
    proj_gemm<<<gprojr, blk>>>(wn, bn, x, pn, CR);

    conv_qk<<<dim3(HW / 64, BB * HEADS), blk>>>(pq, pqh, 0.17677669529663687f);
    conv_qk<<<dim3(HW / 64, BB * HEADS), blk>>>(pk, pkh, 1.0f);
    conv_v<<<NCH / 1024, blk>>>();

    flash_mma<<<dim3(HW / 128, BB * HEADS), blk>>>();

    pa_gemm<<<dim3(HW / 64, HW / 64, BB), blk>>>();
    softmax_rows<<<BB * HW, blk>>>();
    gsa_gemm<<<dim3(HW / 64, CC / 64, BB), blk>>>();

    final_gemm<<<dim3(BB * HW / 64, CC / 64), blk>>>(wo, bo, x, gts, ggs, out);
}

// round 4
// speedup vs baseline: 2.5392x; 1.4227x over previous
#include <cuda_runtime.h>
#include <cuda_bf16.h>
#include <cstdint>

#define BB    2
#define CC    256
#define HW    2304
#define HEADS 8
#define DK    32
#define CR    32
#define NCH   (BB*CC*HW)

// ---------------- scratch (device globals; no allocation) ----------------
__device__ float g_q[NCH];
__device__ float g_k[NCH];
__device__ float g_v[NCH];
__device__ float g_w[NCH];              // wf projection
__device__ float g_mn[BB*64*HW];        // m (rows 0-31) and n (rows 32-63)
__device__ float g_wmn[64*256];
__device__ float g_bmn[64];
__device__ float g_tsa[NCH];
__device__ float g_gsa[NCH];
__device__ float g_pa[(size_t)BB*HW*HW]; // 42.5 MB
__device__ __nv_bfloat16 g_qh[NCH];     // [bh][token][d], pre-scaled
__device__ __nv_bfloat16 g_kh[NCH];     // [bh][token][d]
__device__ __nv_bfloat16 g_vh[NCH];     // [bh][d][token]

// ---------------- fast exp on the FMA pipe ----------------
__device__ __forceinline__ float fexp(float x) {
    float t = x * 1.4426950408889634f;
    t = fmaxf(t, -126.0f);
    float r = t + 12582912.0f;
    int   ii = __float_as_int(r) - 0x4B400000;
    float fi = r - 12582912.0f;
    float f  = t - fi;
    float p  = 1.3333558e-3f;
    p = fmaf(p, f, 9.6181291e-3f);
    p = fmaf(p, f, 5.5504109e-2f);
    p = fmaf(p, f, 2.4022651e-1f);
    p = fmaf(p, f, 6.9314718e-1f);
    p = fmaf(p, f, 1.0f);
    return __int_as_float(__float_as_int(p) + (ii << 23));
}

// ---------------- mma helpers ----------------
__device__ __forceinline__ void mma16816(float* c, const uint32_t* a, uint32_t b0, uint32_t b1) {
    asm volatile(
        "mma.sync.aligned.m16n8k16.row.col.f32.bf16.bf16.f32 "
        "{%0,%1,%2,%3}, {%4,%5,%6,%7}, {%8,%9}, {%0,%1,%2,%3};"
        : "+f"(c[0]), "+f"(c[1]), "+f"(c[2]), "+f"(c[3])
        : "r"(a[0]), "r"(a[1]), "r"(a[2]), "r"(a[3]), "r"(b0), "r"(b1));
}
__device__ __forceinline__ void mma_tf32(float* c, const uint32_t* a, uint32_t b0, uint32_t b1) {
    asm volatile(
        "mma.sync.aligned.m16n8k8.row.col.f32.tf32.tf32.f32 "
        "{%0,%1,%2,%3}, {%4,%5,%6,%7}, {%8,%9}, {%0,%1,%2,%3};"
        : "+f"(c[0]), "+f"(c[1]), "+f"(c[2]), "+f"(c[3])
        : "r"(a[0]), "r"(a[1]), "r"(a[2]), "r"(a[3]), "r"(b0), "r"(b1));
}
__device__ __forceinline__ uint32_t pack_bf16x2(float hi, float lo) {
    uint32_t w;
    asm("cvt.rn.satfinite.bf16x2.f32 %0, %1, %2;" : "=r"(w) : "f"(hi), "f"(lo));
    return w;
}
__device__ __forceinline__ uint32_t cvt_tf32(float f) {
    uint32_t r;
    asm("cvt.rna.tf32.f32 %0, %1;" : "=r"(r) : "f"(f));
    return r;
}
__device__ __forceinline__ uint4 cvt4_tf32(float4 v) {
    uint4 o;
    o.x = cvt_tf32(v.x); o.y = cvt_tf32(v.y); o.z = cvt_tf32(v.z); o.w = cvt_tf32(v.w);
    return o;
}

#define AS_STR 36
#define BS_STR 136

// ---------------- tf32 GEMM: out[b,r,n] = W[r,:]·Bsrc[b,:,n] (+epilogue) ---
// grid (36, 4), block 256 (8 warps: 2m x 4n). Tile 64(M) x 128(N), K=256.
// mode 0: out = acc + bias.  mode 1: out = gt*tsa + gg*(acc+bias) + x.
__global__ void __launch_bounds__(256) tf32_gemm256(
    const float* __restrict__ W, const float* __restrict__ bias,
    const float* __restrict__ Bsrc, float* __restrict__ out, int mode,
    const float* __restrict__ xin, const float* __restrict__ tsa,
    const float* __restrict__ gt_p, const float* __restrict__ gg_p)
{
    __shared__ uint32_t As[64 * AS_STR];
    __shared__ uint32_t Bs[32 * BS_STR];
    int tid = threadIdx.x, lane = tid & 31, wid = tid >> 5;
    int gr = lane >> 2, gc = lane & 3;
    int row0 = blockIdx.y * 64;
    int b = blockIdx.x / 18, hw0 = (blockIdx.x % 18) * 128;
    const float* Bb = Bsrc + (size_t)b * CC * HW + hw0;
    int warpm = wid >> 2, warpn = wid & 3;
    float c[2][4][4];
#pragma unroll
    for (int i = 0; i < 2; i++)
#pragma unroll
        for (int j = 0; j < 4; j++)
#pragma unroll
            for (int k = 0; k < 4; k++) c[i][j][k] = 0.f;

    for (int k0 = 0; k0 < 256; k0 += 32) {
#pragma unroll
        for (int i = 0; i < 2; i++) {
            int e = tid + i * 256;
            int r = e >> 3, k4 = (e & 7) * 4;
            float4 w4 = *(const float4*)(W + (size_t)(row0 + r) * 256 + k0 + k4);
            *(uint4*)(As + r * AS_STR + k4) = cvt4_tf32(w4);
        }
#pragma unroll
        for (int i = 0; i < 4; i++) {
            int e = tid + i * 256;
            int k = e >> 5, n4 = (e & 31) * 4;
            float4 v4 = *(const float4*)(Bb + (size_t)(k0 + k) * HW + n4);
            *(uint4*)(Bs + k * BS_STR + n4) = cvt4_tf32(v4);
        }
        __syncthreads();
#pragma unroll
        for (int ks = 0; ks < 4; ks++) {
            uint32_t a[2][4], bq[4][2];
#pragma unroll
            for (int mt = 0; mt < 2; mt++) {
                const uint32_t* ab = As + (warpm * 32 + mt * 16) * AS_STR + ks * 8 + gc;
                a[mt][0] = ab[gr * AS_STR];
                a[mt][1] = ab[(gr + 8) * AS_STR];
                a[mt][2] = ab[gr * AS_STR + 4];
                a[mt][3] = ab[(gr + 8) * AS_STR + 4];
            }
#pragma unroll
            for (int nt = 0; nt < 4; nt++) {
                const uint32_t* bb = Bs + (ks * 8 + gc) * BS_STR + warpn * 32 + nt * 8 + gr;
                bq[nt][0] = bb[0];
                bq[nt][1] = bb[4 * BS_STR];
            }
#pragma unroll
            for (int mt = 0; mt < 2; mt++)
#pragma unroll
                for (int nt = 0; nt < 4; nt++)
                    mma_tf32(c[mt][nt], a[mt], bq[nt][0], bq[nt][1]);
        }
        __syncthreads();
    }
    float gt = 0.f, gg = 0.f;
    if (mode == 1) { gt = gt_p[0]; gg = gg_p[0]; }
#pragma unroll
    for (int mt = 0; mt < 2; mt++)
#pragma unroll
        for (int rh = 0; rh < 2; rh++) {
            int r = row0 + warpm * 32 + mt * 16 + gr + rh * 8;
            float bv = bias[r];
#pragma unroll
            for (int nt = 0; nt < 4; nt++) {
                int col = hw0 + warpn * 32 + nt * 8 + gc * 2;
                size_t idx = (size_t)b * CC * HW + (size_t)r * HW + col;
                float v0 = c[mt][nt][rh * 2 + 0], v1 = c[mt][nt][rh * 2 + 1];
                float2 o2;
                if (mode == 0) {
                    o2 = make_float2(v0 + bv, v1 + bv);
                } else {
                    float2 x2 = *(const float2*)(xin + idx);
                    float2 t2 = *(const float2*)(tsa + idx);
                    o2.x = gt * t2.x + gg * (v0 + bv) + x2.x;
                    o2.y = gt * t2.y + gg * (v1 + bv) + x2.y;
                }
                *(float2*)(out + idx) = o2;
            }
        }
}

// ---------------- tf32 GSA GEMM: gsa[b,c,n] = sum_m wf[b,c,m]*pa[b,n,m] ---
// grid (36, 4), block 256. Tile 64(c) x 128(n), K=2304 (m).
__global__ void __launch_bounds__(256) tf32_gsa()
{
    __shared__ uint32_t As[64 * AS_STR];
    __shared__ uint32_t Bs[32 * BS_STR];
    int tid = threadIdx.x, lane = tid & 31, wid = tid >> 5;
    int gr = lane >> 2, gc = lane & 3;
    int c0 = blockIdx.y * 64;
    int b = blockIdx.x / 18, n0 = (blockIdx.x % 18) * 128;
    const float* wfb = g_w + (size_t)b * CC * HW;
    const float* pab = g_pa + (size_t)b * HW * HW;
    int warpm = wid >> 2, warpn = wid & 3;
    float c[2][4][4];
#pragma unroll
    for (int i = 0; i < 2; i++)
#pragma unroll
        for (int j = 0; j < 4; j++)
#pragma unroll
            for (int k = 0; k < 4; k++) c[i][j][k] = 0.f;

    for (int m0 = 0; m0 < HW; m0 += 32) {
#pragma unroll
        for (int i = 0; i < 2; i++) {
            int e = tid + i * 256;
            int r = e >> 3, k4 = (e & 7) * 4;
            float4 w4 = *(const float4*)(wfb + (size_t)(c0 + r) * HW + m0 + k4);
            *(uint4*)(As + r * AS_STR + k4) = cvt4_tf32(w4);
        }
#pragma unroll
        for (int i = 0; i < 4; i++) {      // transpose pa tile into Bs[k=m][n]
            int e = tid + i * 256;
            int n = e & 127, k4 = (e >> 7) * 4;
            float4 v4 = *(const float4*)(pab + (size_t)(n0 + n) * HW + m0 + k4);
            Bs[(k4 + 0) * BS_STR + n] = cvt_tf32(v4.x);
            Bs[(k4 + 1) * BS_STR + n] = cvt_tf32(v4.y);
            Bs[(k4 + 2) * BS_STR + n] = cvt_tf32(v4.z);
            Bs[(k4 + 3) * BS_STR + n] = cvt_tf32(v4.w);
        }
        __syncthreads();
#pragma unroll
        for (int ks = 0; ks < 4; ks++) {
            uint32_t a[2][4], bq[4][2];
#pragma unroll
            for (int mt = 0; mt < 2; mt++) {
                const uint32_t* ab = As + (warpm * 32 + mt * 16) * AS_STR + ks * 8 + gc;
                a[mt][0] = ab[gr * AS_STR];
                a[mt][1] = ab[(gr + 8) * AS_STR];
                a[mt][2] = ab[gr * AS_STR + 4];
                a[mt][3] = ab[(gr + 8) * AS_STR + 4];
            }
#pragma unroll
            for (int nt = 0; nt < 4; nt++) {
                const uint32_t* bb = Bs + (ks * 8 + gc) * BS_STR + warpn * 32 + nt * 8 + gr;
                bq[nt][0] = bb[0];
                bq[nt][1] = bb[4 * BS_STR];
            }
#pragma unroll
            for (int mt = 0; mt < 2; mt++)
#pragma unroll
                for (int nt = 0; nt < 4; nt++)
                    mma_tf32(c[mt][nt], a[mt], bq[nt][0], bq[nt][1]);
        }
        __syncthreads();
    }
    float* ob = g_gsa + (size_t)b * CC * HW;
#pragma unroll
    for (int mt = 0; mt < 2; mt++)
#pragma unroll
        for (int rh = 0; rh < 2; rh++) {
            int r = c0 + warpm * 32 + mt * 16 + gr + rh * 8;
#pragma unroll
            for (int nt = 0; nt < 4; nt++) {
                int col = n0 + warpn * 32 + nt * 8 + gc * 2;
                *(float2*)(ob + (size_t)r * HW + col) =
                    make_float2(c[mt][nt][rh * 2 + 0], c[mt][nt][rh * 2 + 1]);
            }
        }
}

// ---------------- fp32 proj (kept for m/n, concentration-sensitive) -------
__global__ void __launch_bounds__(256) proj_gemm(
    const float* __restrict__ W, const float* __restrict__ bias,
    const float* __restrict__ x, float* __restrict__ out, int Co)
{
    __shared__ float As[16][64];
    __shared__ float Bs[16][64];
    int jt  = blockIdx.x;
    int o0  = blockIdx.y * 64;
    int b   = (jt * 64) / HW;
    int hw0 = (jt * 64) % HW;
    const float* xb = x + (size_t)b * CC * HW + hw0;
    int tid = threadIdx.x;
    int tx = tid & 15, ty = tid >> 4;
    float acc[4][4];
#pragma unroll
    for (int i = 0; i < 4; i++)
#pragma unroll
        for (int j = 0; j < 4; j++) acc[i][j] = 0.f;

    int lo  = tid >> 2;
    int lk4 = (tid & 3) * 4;
    int bk  = tid >> 4;
    int bj4 = (tid & 15) * 4;

    for (int k0 = 0; k0 < CC; k0 += 16) {
        float4 wv = make_float4(0.f, 0.f, 0.f, 0.f);
        if (o0 + lo < Co)
            wv = *(const float4*)(W + (size_t)(o0 + lo) * CC + k0 + lk4);
        As[lk4 + 0][lo] = wv.x; As[lk4 + 1][lo] = wv.y;
        As[lk4 + 2][lo] = wv.z; As[lk4 + 3][lo] = wv.w;
        float4 xv = *(const float4*)(xb + (size_t)(k0 + bk) * HW + bj4);
        *(float4*)&Bs[bk][bj4] = xv;
        __syncthreads();
#pragma unroll
        for (int k = 0; k < 16; k++) {
            float4 a  = *(float4*)&As[k][ty * 4];
            float4 bb = *(float4*)&Bs[k][tx * 4];
            float av[4] = {a.x, a.y, a.z, a.w};
            float bv[4] = {bb.x, bb.y, bb.z, bb.w};
#pragma unroll
            for (int i = 0; i < 4; i++)
#pragma unroll
                for (int j = 0; j < 4; j++)
                    acc[i][j] = fmaf(av[i], bv[j], acc[i][j]);
        }
        __syncthreads();
    }
#pragma unroll
    for (int i = 0; i < 4; i++) {
        int o = o0 + ty * 4 + i;
        if (o < Co) {
            float bsv = bias[o];
            float4 ov = make_float4(acc[i][0] + bsv, acc[i][1] + bsv,
                                    acc[i][2] + bsv, acc[i][3] + bsv);
            *(float4*)(out + (size_t)b * Co * HW + (size_t)o * HW + hw0 + tx * 4) = ov;
        }
    }
}

__global__ void __launch_bounds__(256) concat_mn(
    const float* __restrict__ wm, const float* __restrict__ bm,
    const float* __restrict__ wn, const float* __restrict__ bn)
{
    int i = blockIdx.x * 256 + threadIdx.x;
    if (i < 32 * 256) { g_wmn[i] = wm[i]; g_wmn[32 * 256 + i] = wn[i]; }
    if (i < 32) { g_bmn[i] = bm[i]; g_bmn[32 + i] = bn[i]; }
}

// ---------------- converters for the tensor-core flash ----------------
__global__ void __launch_bounds__(256) conv_qk(
    const float* __restrict__ src, __nv_bfloat16* __restrict__ dst, float scale)
{
    __shared__ float t[32][65];
    int bh = blockIdx.y;
    int t0 = blockIdx.x * 64;
    const float* s = src + (size_t)bh * 32 * HW + t0;
    int tid = threadIdx.x;
    for (int e = tid; e < 2048; e += 256) {
        int d = e >> 6, tt = e & 63;
        t[d][tt] = s[(size_t)d * HW + tt] * scale;
    }
    __syncthreads();
    int j = tid >> 2, seg = (tid & 3) * 8;
    __nv_bfloat16 tmp[8];
#pragma unroll
    for (int i = 0; i < 8; i++) tmp[i] = __float2bfloat16(t[seg + i][j]);
    *(uint4*)(dst + ((size_t)bh * HW + t0 + j) * DK + seg) = *(uint4*)tmp;
}

__global__ void __launch_bounds__(256) conv_v()
{
    size_t i = ((size_t)blockIdx.x * 256 + threadIdx.x) * 4;
    float4 v = *(const float4*)(g_v + i);
    __nv_bfloat16 t[4];
    t[0] = __float2bfloat16(v.x); t[1] = __float2bfloat16(v.y);
    t[2] = __float2bfloat16(v.z); t[3] = __float2bfloat16(v.w);
    *(uint2*)(g_vh + i) = *(uint2*)t;
}

// ---------------- FA2-style flash TSA with mma.sync bf16 ----------------
#define QS_STR 40
#define VS_STR 136
__global__ void __launch_bounds__(256) flash_mma()
{
    __shared__ __nv_bfloat16 Qs[128 * QS_STR];
    __shared__ __nv_bfloat16 Ks[128 * QS_STR];
    __shared__ __nv_bfloat16 Vs[32 * VS_STR];
    int tid = threadIdx.x, wid = tid >> 5, lane = tid & 31;
    int bh = blockIdx.y, i0 = blockIdx.x * 128;
    int gr = lane >> 2, gc = (lane & 3) * 2;

    const __nv_bfloat16* qsrc = g_qh + ((size_t)bh * HW + i0) * DK;
    const __nv_bfloat16* ksrc = g_kh + (size_t)bh * HW * DK;
    const __nv_bfloat16* vsrc = g_vh + (size_t)bh * DK * HW;

    for (int e = tid; e < 512; e += 256) {
        int r = e >> 2, c8 = (e & 3) * 8;
        *(uint4*)(Qs + r * QS_STR + c8) = *(const uint4*)(qsrc + r * DK + c8);
    }
    __syncthreads();

    uint32_t qa[2][4];
    {
        const __nv_bfloat16* qb = Qs + (wid * 16 + gr) * QS_STR;
#pragma unroll
        for (int kc = 0; kc < 2; kc++) {
            qa[kc][0] = *(const uint32_t*)(qb + kc * 16 + gc);
            qa[kc][1] = *(const uint32_t*)(qb + 8 * QS_STR + kc * 16 + gc);
            qa[kc][2] = *(const uint32_t*)(qb + kc * 16 + gc + 8);
            qa[kc][3] = *(const uint32_t*)(qb + 8 * QS_STR + kc * 16 + gc + 8);
        }
    }

    float o[4][4];
#pragma unroll
    for (int i = 0; i < 4; i++)
#pragma unroll
        for (int j = 0; j < 4; j++) o[i][j] = 0.f;
    float l0 = 0.f, l1 = 0.f;

    for (int kt = 0; kt < 18; kt++) {
        int j0 = kt * 128;
        __syncthreads();
        for (int e = tid; e < 512; e += 256) {
            int r = e >> 2, c8 = (e & 3) * 8;
            *(uint4*)(Ks + r * QS_STR + c8) = *(const uint4*)(ksrc + (size_t)(j0 + r) * DK + c8);
        }
        for (int e = tid; e < 512; e += 256) {
            int d = e >> 4, c8 = (e & 15) * 8;
            *(uint4*)(Vs + d * VS_STR + c8) = *(const uint4*)(vsrc + (size_t)d * HW + j0 + c8);
        }
        __syncthreads();

        float s[16][4];
#pragma unroll
        for (int nt = 0; nt < 16; nt++) {
            s[nt][0] = 0.f; s[nt][1] = 0.f; s[nt][2] = 0.f; s[nt][3] = 0.f;
            const __nv_bfloat16* kb = Ks + (nt * 8 + gr) * QS_STR;
#pragma unroll
            for (int kc = 0; kc < 2; kc++) {
                uint32_t b0 = *(const uint32_t*)(kb + kc * 16 + gc);
                uint32_t b1 = *(const uint32_t*)(kb + kc * 16 + gc + 8);
                mma16816(s[nt], qa[kc], b0, b1);
            }
        }

        uint32_t pa_[8][4];
#pragma unroll
        for (int h2 = 0; h2 < 8; h2++) {
            float e00 = __expf(s[2 * h2][0]),     e01 = __expf(s[2 * h2][1]);
            float e02 = __expf(s[2 * h2][2]),     e03 = __expf(s[2 * h2][3]);
            float f00 = __expf(s[2 * h2 + 1][0]), f01 = __expf(s[2 * h2 + 1][1]);
            float f02 = __expf(s[2 * h2 + 1][2]), f03 = __expf(s[2 * h2 + 1][3]);
            l0 += (e00 + e01) + (f00 + f01);
            l1 += (e02 + e03) + (f02 + f03);
            pa_[h2][0] = pack_bf16x2(e01, e00);
            pa_[h2][1] = pack_bf16x2(e03, e02);
            pa_[h2][2] = pack_bf16x2(f01, f00);
            pa_[h2][3] = pack_bf16x2(f03, f02);
        }

#pragma unroll
        for (int kc2 = 0; kc2 < 8; kc2++) {
#pragma unroll
            for (int dt = 0; dt < 4; dt++) {
                const __nv_bfloat16* vb = Vs + (dt * 8 + gr) * VS_STR + kc2 * 16 + gc;
                uint32_t b0 = *(const uint32_t*)(vb);
                uint32_t b1 = *(const uint32_t*)(vb + 8);
                mma16816(o[dt], pa_[kc2], b0, b1);
            }
        }
    }

    l0 += __shfl_xor_sync(0xffffffffu, l0, 1);
    l0 += __shfl_xor_sync(0xffffffffu, l0, 2);
    l1 += __shfl_xor_sync(0xffffffffu, l1, 1);
    l1 += __shfl_xor_sync(0xffffffffu, l1, 2);
    float inv0 = 1.f / l0, inv1 = 1.f / l1;

    int b = bh >> 3, h = bh & 7;
    float* ob = g_tsa + ((size_t)b * CC + h * DK) * HW;
    int tok0 = i0 + wid * 16 + gr;
#pragma unroll
    for (int dt = 0; dt < 4; dt++) {
        int d = dt * 8 + gc;
        ob[(size_t)(d)     * HW + tok0]     = o[dt][0] * inv0;
        ob[(size_t)(d + 1) * HW + tok0]     = o[dt][1] * inv0;
        ob[(size_t)(d)     * HW + tok0 + 8] = o[dt][2] * inv1;
        ob[(size_t)(d + 1) * HW + tok0 + 8] = o[dt][3] * inv1;
    }
}

// ---------------- GSA raw scores (fp32) ----------------
__global__ void __launch_bounds__(256) pa_gemm()
{
    __shared__ float Ms[32][64];
    __shared__ float Ns[32][64];
    int b  = blockIdx.z;
    int i0 = blockIdx.x * 64;
    int j0 = blockIdx.y * 64;
    const float* mb_ = g_mn + (size_t)b * 64 * HW;
    const float* nb  = mb_ + (size_t)32 * HW;
    int tid = threadIdx.x;
    int tx = tid & 15, ty = tid >> 4;
    for (int e = tid; e < 2048; e += 256) {
        int c = e >> 6, i = e & 63;
        Ms[c][i] = mb_[(size_t)c * HW + i0 + i];
        Ns[c][i] = nb[(size_t)c * HW + j0 + i];
    }
    __syncthreads();
    float acc[4][4];
#pragma unroll
    for (int i = 0; i < 4; i++)
#pragma unroll
        for (int j = 0; j < 4; j++) acc[i][j] = 0.f;
#pragma unroll
    for (int c = 0; c < 32; c++) {
        float4 a  = *(float4*)&Ms[c][ty * 4];
        float4 nn = *(float4*)&Ns[c][tx * 4];
        float av[4] = {a.x, a.y, a.z, a.w};
        float nv[4] = {nn.x, nn.y, nn.z, nn.w};
#pragma unroll
        for (int i = 0; i < 4; i++)
#pragma unroll
            for (int j = 0; j < 4; j++)
                acc[i][j] = fmaf(av[i], nv[j], acc[i][j]);
    }
    float* pb = g_pa + (size_t)b * HW * HW;
#pragma unroll
    for (int i = 0; i < 4; i++) {
        float4 ov = make_float4(acc[i][0], acc[i][1], acc[i][2], acc[i][3]);
        *(float4*)(pb + (size_t)(i0 + ty * 4 + i) * HW + j0 + tx * 4) = ov;
    }
}

// ---------------- row softmax over pa (in place) ----------------
__global__ void __launch_bounds__(256) softmax_rows()
{
    __shared__ float red[8];
    size_t row = blockIdx.x;
    float* p = g_pa + row * HW;
    int tid = threadIdx.x;
    float v[9];
    float mx = -1e30f;
#pragma unroll
    for (int e = 0; e < 9; e++) { v[e] = p[tid + 256 * e]; mx = fmaxf(mx, v[e]); }
#pragma unroll
    for (int off = 16; off; off >>= 1)
        mx = fmaxf(mx, __shfl_xor_sync(0xffffffffu, mx, off));
    if ((tid & 31) == 0) red[tid >> 5] = mx;
    __syncthreads();
    float m8 = red[0];
#pragma unroll
    for (int i = 1; i < 8; i++) m8 = fmaxf(m8, red[i]);
    float s = 0.f;
#pragma unroll
    for (int e = 0; e < 9; e++) { v[e] = fexp(v[e] - m8); s += v[e]; }
#pragma unroll
    for (int off = 16; off; off >>= 1)
        s += __shfl_xor_sync(0xffffffffu, s, off);
    __syncthreads();
    if ((tid & 31) == 0) red[tid >> 5] = s;
    __syncthreads();
    float s8 = 0.f;
#pragma unroll
    for (int i = 0; i < 8; i++) s8 += red[i];
    float inv = 1.f / s8;
#pragma unroll
    for (int e = 0; e < 9; e++) p[tid + 256 * e] = v[e] * inv;
}

// ---------------- launch ----------------
extern "C" void kernel_launch(void* const* d_in, const int* in_sizes, int n_in,
                              void* d_out, int out_size)
{
    const float* x   = (const float*)d_in[0];
    const float* wq  = (const float*)d_in[1];
    const float* bq  = (const float*)d_in[2];
    const float* wk  = (const float*)d_in[3];
    const float* bk  = (const float*)d_in[4];
    const float* wv  = (const float*)d_in[5];
    const float* bv  = (const float*)d_in[6];
    const float* wm  = (const float*)d_in[7];
    const float* bm  = (const float*)d_in[8];
    const float* wn  = (const float*)d_in[9];
    const float* bn  = (const float*)d_in[10];
    const float* ww  = (const float*)d_in[11];
    const float* bw  = (const float*)d_in[12];
    const float* wo  = (const float*)d_in[13];
    const float* bo  = (const float*)d_in[14];
    const float* gts = (const float*)d_in[15];
    const float* ggs = (const float*)d_in[16];
    float* out = (float*)d_out;

    float *pq, *pk, *pv, *pw, *pmn, *pwmn, *pbmn, *ptsa, *pgsa;
    __nv_bfloat16 *pqh, *pkh;
    cudaGetSymbolAddress((void**)&pq, g_q);
    cudaGetSymbolAddress((void**)&pk, g_k);
    cudaGetSymbolAddress((void**)&pv, g_v);
    cudaGetSymbolAddress((void**)&pw, g_w);
    cudaGetSymbolAddress((void**)&pmn, g_mn);
    cudaGetSymbolAddress((void**)&pwmn, g_wmn);
    cudaGetSymbolAddress((void**)&pbmn, g_bmn);
    cudaGetSymbolAddress((void**)&ptsa, g_tsa);
    cudaGetSymbolAddress((void**)&pgsa, g_gsa);
    cudaGetSymbolAddress((void**)&pqh, g_qh);
    cudaGetSymbolAddress((void**)&pkh, g_kh);

    dim3 blk(256);
    dim3 gtf(36, 4);

    concat_mn<<<32, blk>>>(wm, bm, wn, bn);

    tf32_gemm256<<<gtf, blk>>>(wq, bq, x, pq, 0, nullptr, nullptr, nullptr, nullptr);
    tf32_gemm256<<<gtf, blk>>>(wk, bk, x, pk, 0, nullptr, nullptr, nullptr, nullptr);
    tf32_gemm256<<<gtf, blk>>>(wv, bv, x, pv, 0, nullptr, nullptr, nullptr, nullptr);
    tf32_gemm256<<<gtf, blk>>>(ww, bw, x, pw, 0, nullptr, nullptr, nullptr, nullptr);
    proj_gemm<<<dim3(BB * HW / 64, 1), blk>>>(pwmn, pbmn, x, pmn, 64);

    conv_qk<<<dim3(HW / 64, BB * HEADS), blk>>>(pq, pqh, 0.17677669529663687f);
    conv_qk<<<dim3(HW / 64, BB * HEADS), blk>>>(pk, pkh, 1.0f);
    conv_v<<<NCH / 1024, blk>>>();

    flash_mma<<<dim3(HW / 128, BB * HEADS), blk>>>();

    pa_gemm<<<dim3(HW / 64, HW / 64, BB), blk>>>();
    softmax_rows<<<BB * HW, blk>>>();
    tf32_gsa<<<gtf, blk>>>();

    tf32_gemm256<<<gtf, blk>>>(wo, bo, pgsa, out, 1, x, ptsa, gts, ggs);
}

// round 5
// speedup vs baseline: 3.0461x; 1.1996x over previous
#include <cuda_runtime.h>
#include <cuda_bf16.h>
#include <cstdint>

#define BB    2
#define CC    256
#define HW    2304
#define HEADS 8
#define DK    32
#define CR    32
#define NCH   (BB*CC*HW)

// ---------------- scratch (device globals; no allocation) ----------------
__device__ float g_q[NCH];
__device__ float g_k[NCH];
__device__ float g_v[NCH];
__device__ float g_w[NCH];              // wf projection
__device__ float g_mn[BB*64*HW];        // m (rows 0-31) and n (rows 32-63)
__device__ float g_wmn[64*256];
__device__ float g_bmn[64];
__device__ float g_tsa[NCH];
__device__ float g_gsa[NCH];
__device__ float g_pa[(size_t)BB*HW*HW]; // 42.5 MB
__device__ __nv_bfloat16 g_qh[NCH];
__device__ __nv_bfloat16 g_kh[NCH];
__device__ __nv_bfloat16 g_vh[NCH];

// ---------------- fast exp on the FMA pipe ----------------
__device__ __forceinline__ float fexp(float x) {
    float t = x * 1.4426950408889634f;
    t = fmaxf(t, -126.0f);
    float r = t + 12582912.0f;
    int   ii = __float_as_int(r) - 0x4B400000;
    float fi = r - 12582912.0f;
    float f  = t - fi;
    float p  = 1.3333558e-3f;
    p = fmaf(p, f, 9.6181291e-3f);
    p = fmaf(p, f, 5.5504109e-2f);
    p = fmaf(p, f, 2.4022651e-1f);
    p = fmaf(p, f, 6.9314718e-1f);
    p = fmaf(p, f, 1.0f);
    return __int_as_float(__float_as_int(p) + (ii << 23));
}

// ---------------- mma helpers ----------------
__device__ __forceinline__ void mma16816(float* c, const uint32_t* a, uint32_t b0, uint32_t b1) {
    asm volatile(
        "mma.sync.aligned.m16n8k16.row.col.f32.bf16.bf16.f32 "
        "{%0,%1,%2,%3}, {%4,%5,%6,%7}, {%8,%9}, {%0,%1,%2,%3};"
        : "+f"(c[0]), "+f"(c[1]), "+f"(c[2]), "+f"(c[3])
        : "r"(a[0]), "r"(a[1]), "r"(a[2]), "r"(a[3]), "r"(b0), "r"(b1));
}
__device__ __forceinline__ void mma_tf32(float* c, const uint32_t* a, uint32_t b0, uint32_t b1) {
    asm volatile(
        "mma.sync.aligned.m16n8k8.row.col.f32.tf32.tf32.f32 "
        "{%0,%1,%2,%3}, {%4,%5,%6,%7}, {%8,%9}, {%0,%1,%2,%3};"
        : "+f"(c[0]), "+f"(c[1]), "+f"(c[2]), "+f"(c[3])
        : "r"(a[0]), "r"(a[1]), "r"(a[2]), "r"(a[3]), "r"(b0), "r"(b1));
}
__device__ __forceinline__ uint32_t pack_bf16x2(float hi, float lo) {
    uint32_t w;
    asm("cvt.rn.satfinite.bf16x2.f32 %0, %1, %2;" : "=r"(w) : "f"(hi), "f"(lo));
    return w;
}
__device__ __forceinline__ uint32_t cvt_tf32(float f) {
    uint32_t r;
    asm("cvt.rna.tf32.f32 %0, %1;" : "=r"(r) : "f"(f));
    return r;
}
__device__ __forceinline__ uint4 cvt4_tf32(float4 v) {
    uint4 o;
    o.x = cvt_tf32(v.x); o.y = cvt_tf32(v.y); o.z = cvt_tf32(v.z); o.w = cvt_tf32(v.w);
    return o;
}

#define AS_STR 36
#define BS_STR 136
#define ASZ (64 * AS_STR)
#define BSZ (32 * BS_STR)

// compute one K=32 chunk of the 64x128 tile (shared by all tf32 gemms)
__device__ __forceinline__ void tf32_chunk(
    const uint32_t* Ap, const uint32_t* Bp, float c[2][4][4],
    int warpm, int warpn, int gr, int gc)
{
#pragma unroll
    for (int ks = 0; ks < 4; ks++) {
        uint32_t a[2][4], bq[4][2];
#pragma unroll
        for (int mt = 0; mt < 2; mt++) {
            const uint32_t* ab = Ap + (warpm * 32 + mt * 16) * AS_STR + ks * 8 + gc;
            a[mt][0] = ab[gr * AS_STR];
            a[mt][1] = ab[(gr + 8) * AS_STR];
            a[mt][2] = ab[gr * AS_STR + 4];
            a[mt][3] = ab[(gr + 8) * AS_STR + 4];
        }
#pragma unroll
        for (int nt = 0; nt < 4; nt++) {
            const uint32_t* bb = Bp + (ks * 8 + gc) * BS_STR + warpn * 32 + nt * 8 + gr;
            bq[nt][0] = bb[0];
            bq[nt][1] = bb[4 * BS_STR];
        }
#pragma unroll
        for (int mt = 0; mt < 2; mt++)
#pragma unroll
            for (int nt = 0; nt < 4; nt++)
                mma_tf32(c[mt][nt], a[mt], bq[nt][0], bq[nt][1]);
    }
}

// ---------------- fused QKVW projection: 4 GEMMs in one launch ------------
// grid (36, 16), block 256. blockIdx.y>>2 selects which of q/k/v/w.
__global__ void __launch_bounds__(256) tf32_proj4(
    const float* __restrict__ wq, const float* __restrict__ bq,
    const float* __restrict__ wk, const float* __restrict__ bk,
    const float* __restrict__ wv, const float* __restrict__ bv,
    const float* __restrict__ ww, const float* __restrict__ bw,
    const float* __restrict__ x)
{
    __shared__ uint32_t As[ASZ];
    __shared__ uint32_t Bs[BSZ];
    int tid = threadIdx.x, lane = tid & 31, wid = tid >> 5;
    int gr = lane >> 2, gc = lane & 3;
    int sel  = blockIdx.y >> 2;
    int row0 = (blockIdx.y & 3) * 64;
    const float* W    = sel == 0 ? wq : sel == 1 ? wk : sel == 2 ? wv : ww;
    const float* bias = sel == 0 ? bq : sel == 1 ? bk : sel == 2 ? bv : bw;
    float* out;
    {
        float *p0 = g_q, *p1 = g_k, *p2 = g_v, *p3 = g_w;
        out = sel == 0 ? p0 : sel == 1 ? p1 : sel == 2 ? p2 : p3;
    }
    int b = blockIdx.x / 18, hw0 = (blockIdx.x % 18) * 128;
    const float* Bb = x + (size_t)b * CC * HW + hw0;
    int warpm = wid >> 2, warpn = wid & 3;
    float c[2][4][4];
#pragma unroll
    for (int i = 0; i < 2; i++)
#pragma unroll
        for (int j = 0; j < 4; j++)
#pragma unroll
            for (int k = 0; k < 4; k++) c[i][j][k] = 0.f;

    for (int k0 = 0; k0 < 256; k0 += 32) {
#pragma unroll
        for (int i = 0; i < 2; i++) {
            int e = tid + i * 256;
            int r = e >> 3, k4 = (e & 7) * 4;
            float4 w4 = *(const float4*)(W + (size_t)(row0 + r) * 256 + k0 + k4);
            *(uint4*)(As + r * AS_STR + k4) = cvt4_tf32(w4);
        }
#pragma unroll
        for (int i = 0; i < 4; i++) {
            int e = tid + i * 256;
            int k = e >> 5, n4 = (e & 31) * 4;
            float4 v4 = *(const float4*)(Bb + (size_t)(k0 + k) * HW + n4);
            *(uint4*)(Bs + k * BS_STR + n4) = cvt4_tf32(v4);
        }
        __syncthreads();
        tf32_chunk(As, Bs, c, warpm, warpn, gr, gc);
        __syncthreads();
    }
#pragma unroll
    for (int mt = 0; mt < 2; mt++)
#pragma unroll
        for (int rh = 0; rh < 2; rh++) {
            int r = row0 + warpm * 32 + mt * 16 + gr + rh * 8;
            float bv2 = bias[r];
#pragma unroll
            for (int nt = 0; nt < 4; nt++) {
                int col = hw0 + warpn * 32 + nt * 8 + gc * 2;
                size_t idx = (size_t)b * CC * HW + (size_t)r * HW + col;
                *(float2*)(out + idx) = make_float2(c[mt][nt][rh * 2 + 0] + bv2,
                                                    c[mt][nt][rh * 2 + 1] + bv2);
            }
        }
}

// ---------------- double-buffered tf32 GSA: gsa = wf @ pa^T ---------------
// grid (36, 4), block 256, dynamic smem 52KB. K=2304.
__global__ void __launch_bounds__(256) tf32_gsa()
{
    extern __shared__ uint32_t dsm[];
    uint32_t* As = dsm;            // [2][ASZ]
    uint32_t* Bs = dsm + 2 * ASZ;  // [2][BSZ]
    int tid = threadIdx.x, lane = tid & 31, wid = tid >> 5;
    int gr = lane >> 2, gc = lane & 3;
    int c0 = blockIdx.y * 64;
    int b = blockIdx.x / 18, n0 = (blockIdx.x % 18) * 128;
    const float* wfb = g_w + (size_t)b * CC * HW;
    const float* pab = g_pa + (size_t)b * HW * HW;
    int warpm = wid >> 2, warpn = wid & 3;

    int ar = tid >> 3, ak4 = (tid & 7) * 4;          // A elem 0 (e=tid)
    int ar2 = (tid + 256) >> 3;                      // A elem 1
    int bn = tid & 127, bk4_0 = (tid >> 7) * 4;      // B elems: k4 = bk4_0 + i*8? no:
    // B: e = tid + i*256 -> n = e&127 (same for all i), k4 = (e>>7)*4 = bk4_0 + i*8

    float4 ra[2], rb[4];
    // prologue: load chunk 0
#pragma unroll
    for (int i = 0; i < 2; i++) {
        int r = (i == 0) ? ar : ar2;
        ra[i] = *(const float4*)(wfb + (size_t)(c0 + r) * HW + 0 + ak4);
    }
#pragma unroll
    for (int i = 0; i < 4; i++)
        rb[i] = *(const float4*)(pab + (size_t)(n0 + bn) * HW + 0 + (bk4_0 + i * 8));
#pragma unroll
    for (int i = 0; i < 2; i++) {
        int r = (i == 0) ? ar : ar2;
        *(uint4*)(As + r * AS_STR + ak4) = cvt4_tf32(ra[i]);
    }
#pragma unroll
    for (int i = 0; i < 4; i++) {
        int k4 = bk4_0 + i * 8;
        Bs[(k4 + 0) * BS_STR + bn] = cvt_tf32(rb[i].x);
        Bs[(k4 + 1) * BS_STR + bn] = cvt_tf32(rb[i].y);
        Bs[(k4 + 2) * BS_STR + bn] = cvt_tf32(rb[i].z);
        Bs[(k4 + 3) * BS_STR + bn] = cvt_tf32(rb[i].w);
    }
    __syncthreads();

    float c[2][4][4];
#pragma unroll
    for (int i = 0; i < 2; i++)
#pragma unroll
        for (int j = 0; j < 4; j++)
#pragma unroll
            for (int k = 0; k < 4; k++) c[i][j][k] = 0.f;

    for (int it = 0; it < 72; it++) {
        int p = it & 1;
        int m1 = (it + 1) * 32;
        if (it + 1 < 72) {
#pragma unroll
            for (int i = 0; i < 2; i++) {
                int r = (i == 0) ? ar : ar2;
                ra[i] = *(const float4*)(wfb + (size_t)(c0 + r) * HW + m1 + ak4);
            }
#pragma unroll
            for (int i = 0; i < 4; i++)
                rb[i] = *(const float4*)(pab + (size_t)(n0 + bn) * HW + m1 + (bk4_0 + i * 8));
        }
        tf32_chunk(As + p * ASZ, Bs + p * BSZ, c, warpm, warpn, gr, gc);
        if (it + 1 < 72) {
            uint32_t* Ad = As + (p ^ 1) * ASZ;
            uint32_t* Bd = Bs + (p ^ 1) * BSZ;
#pragma unroll
            for (int i = 0; i < 2; i++) {
                int r = (i == 0) ? ar : ar2;
                *(uint4*)(Ad + r * AS_STR + ak4) = cvt4_tf32(ra[i]);
            }
#pragma unroll
            for (int i = 0; i < 4; i++) {
                int k4 = bk4_0 + i * 8;
                Bd[(k4 + 0) * BS_STR + bn] = cvt_tf32(rb[i].x);
                Bd[(k4 + 1) * BS_STR + bn] = cvt_tf32(rb[i].y);
                Bd[(k4 + 2) * BS_STR + bn] = cvt_tf32(rb[i].z);
                Bd[(k4 + 3) * BS_STR + bn] = cvt_tf32(rb[i].w);
            }
        }
        __syncthreads();
    }

    float* ob = g_gsa + (size_t)b * CC * HW;
#pragma unroll
    for (int mt = 0; mt < 2; mt++)
#pragma unroll
        for (int rh = 0; rh < 2; rh++) {
            int r = c0 + warpm * 32 + mt * 16 + gr + rh * 8;
#pragma unroll
            for (int nt = 0; nt < 4; nt++) {
                int col = n0 + warpn * 32 + nt * 8 + gc * 2;
                *(float2*)(ob + (size_t)r * HW + col) =
                    make_float2(c[mt][nt][rh * 2 + 0], c[mt][nt][rh * 2 + 1]);
            }
        }
}

// ---------------- double-buffered final GEMM + fusion epilogue ------------
// grid (36, 4), block 256, dynamic smem. out = gt*tsa + gg*(wo@gsa+bo) + x.
__global__ void __launch_bounds__(256) tf32_final(
    const float* __restrict__ wo, const float* __restrict__ bo,
    const float* __restrict__ xin,
    const float* __restrict__ gt_p, const float* __restrict__ gg_p,
    float* __restrict__ out)
{
    extern __shared__ uint32_t dsm[];
    uint32_t* As = dsm;
    uint32_t* Bs = dsm + 2 * ASZ;
    int tid = threadIdx.x, lane = tid & 31, wid = tid >> 5;
    int gr = lane >> 2, gc = lane & 3;
    int row0 = blockIdx.y * 64;
    int b = blockIdx.x / 18, hw0 = (blockIdx.x % 18) * 128;
    const float* Bb = g_gsa + (size_t)b * CC * HW + hw0;
    int warpm = wid >> 2, warpn = wid & 3;

    int ar = tid >> 3, ak4 = (tid & 7) * 4;
    int ar2 = (tid + 256) >> 3;
    int bk = tid >> 5, bn4 = (tid & 31) * 4;   // B: e=tid+i*256 -> k = bk + i*8

    float4 ra[2], rb[4];
#pragma unroll
    for (int i = 0; i < 2; i++) {
        int r = (i == 0) ? ar : ar2;
        ra[i] = *(const float4*)(wo + (size_t)(row0 + r) * 256 + 0 + ak4);
    }
#pragma unroll
    for (int i = 0; i < 4; i++)
        rb[i] = *(const float4*)(Bb + (size_t)(0 + bk + i * 8) * HW + bn4);
#pragma unroll
    for (int i = 0; i < 2; i++) {
        int r = (i == 0) ? ar : ar2;
        *(uint4*)(As + r * AS_STR + ak4) = cvt4_tf32(ra[i]);
    }
#pragma unroll
    for (int i = 0; i < 4; i++)
        *(uint4*)(Bs + (bk + i * 8) * BS_STR + bn4) = cvt4_tf32(rb[i]);
    __syncthreads();

    float c[2][4][4];
#pragma unroll
    for (int i = 0; i < 2; i++)
#pragma unroll
        for (int j = 0; j < 4; j++)
#pragma unroll
            for (int k = 0; k < 4; k++) c[i][j][k] = 0.f;

    for (int it = 0; it < 8; it++) {
        int p = it & 1;
        int k1 = (it + 1) * 32;
        if (it + 1 < 8) {
#pragma unroll
            for (int i = 0; i < 2; i++) {
                int r = (i == 0) ? ar : ar2;
                ra[i] = *(const float4*)(wo + (size_t)(row0 + r) * 256 + k1 + ak4);
            }
#pragma unroll
            for (int i = 0; i < 4; i++)
                rb[i] = *(const float4*)(Bb + (size_t)(k1 + bk + i * 8) * HW + bn4);
        }
        tf32_chunk(As + p * ASZ, Bs + p * BSZ, c, warpm, warpn, gr, gc);
        if (it + 1 < 8) {
            uint32_t* Ad = As + (p ^ 1) * ASZ;
            uint32_t* Bd = Bs + (p ^ 1) * BSZ;
#pragma unroll
            for (int i = 0; i < 2; i++) {
                int r = (i == 0) ? ar : ar2;
                *(uint4*)(Ad + r * AS_STR + ak4) = cvt4_tf32(ra[i]);
            }
#pragma unroll
            for (int i = 0; i < 4; i++)
                *(uint4*)(Bd + (bk + i * 8) * BS_STR + bn4) = cvt4_tf32(rb[i]);
        }
        __syncthreads();
    }

    float gt = gt_p[0], gg = gg_p[0];
#pragma unroll
    for (int mt = 0; mt < 2; mt++)
#pragma unroll
        for (int rh = 0; rh < 2; rh++) {
            int r = row0 + warpm * 32 + mt * 16 + gr + rh * 8;
            float bv = bo[r];
#pragma unroll
            for (int nt = 0; nt < 4; nt++) {
                int col = hw0 + warpn * 32 + nt * 8 + gc * 2;
                size_t idx = (size_t)b * CC * HW + (size_t)r * HW + col;
                float2 x2 = *(const float2*)(xin + idx);
                float2 t2 = *(const float2*)(g_tsa + idx);
                float2 o2;
                o2.x = gt * t2.x + gg * (c[mt][nt][rh * 2 + 0] + bv) + x2.x;
                o2.y = gt * t2.y + gg * (c[mt][nt][rh * 2 + 1] + bv) + x2.y;
                *(float2*)(out + idx) = o2;
            }
        }
}

// ---------------- fp32 proj (m/n, concentration-sensitive) ----------------
__global__ void __launch_bounds__(256) proj_gemm(
    const float* __restrict__ W, const float* __restrict__ bias,
    const float* __restrict__ x, float* __restrict__ out, int Co)
{
    __shared__ float As[16][64];
    __shared__ float Bs[16][64];
    int jt  = blockIdx.x;
    int o0  = blockIdx.y * 64;
    int b   = (jt * 64) / HW;
    int hw0 = (jt * 64) % HW;
    const float* xb = x + (size_t)b * CC * HW + hw0;
    int tid = threadIdx.x;
    int tx = tid & 15, ty = tid >> 4;
    float acc[4][4];
#pragma unroll
    for (int i = 0; i < 4; i++)
#pragma unroll
        for (int j = 0; j < 4; j++) acc[i][j] = 0.f;

    int lo  = tid >> 2;
    int lk4 = (tid & 3) * 4;
    int bk  = tid >> 4;
    int bj4 = (tid & 15) * 4;

    for (int k0 = 0; k0 < CC; k0 += 16) {
        float4 wv = make_float4(0.f, 0.f, 0.f, 0.f);
        if (o0 + lo < Co)
            wv = *(const float4*)(W + (size_t)(o0 + lo) * CC + k0 + lk4);
        As[lk4 + 0][lo] = wv.x; As[lk4 + 1][lo] = wv.y;
        As[lk4 + 2][lo] = wv.z; As[lk4 + 3][lo] = wv.w;
        float4 xv = *(const float4*)(xb + (size_t)(k0 + bk) * HW + bj4);
        *(float4*)&Bs[bk][bj4] = xv;
        __syncthreads();
#pragma unroll
        for (int k = 0; k < 16; k++) {
            float4 a  = *(float4*)&As[k][ty * 4];
            float4 bb = *(float4*)&Bs[k][tx * 4];
            float av[4] = {a.x, a.y, a.z, a.w};
            float bv[4] = {bb.x, bb.y, bb.z, bb.w};
#pragma unroll
            for (int i = 0; i < 4; i++)
#pragma unroll
                for (int j = 0; j < 4; j++)
                    acc[i][j] = fmaf(av[i], bv[j], acc[i][j]);
        }
        __syncthreads();
    }
#pragma unroll
    for (int i = 0; i < 4; i++) {
        int o = o0 + ty * 4 + i;
        if (o < Co) {
            float bsv = bias[o];
            float4 ov = make_float4(acc[i][0] + bsv, acc[i][1] + bsv,
                                    acc[i][2] + bsv, acc[i][3] + bsv);
            *(float4*)(out + (size_t)b * Co * HW + (size_t)o * HW + hw0 + tx * 4) = ov;
        }
    }
}

__global__ void __launch_bounds__(256) concat_mn(
    const float* __restrict__ wm, const float* __restrict__ bm,
    const float* __restrict__ wn, const float* __restrict__ bn)
{
    int i = blockIdx.x * 256 + threadIdx.x;
    if (i < 32 * 256) { g_wmn[i] = wm[i]; g_wmn[32 * 256 + i] = wn[i]; }
    if (i < 32) { g_bmn[i] = bm[i]; g_bmn[32 + i] = bn[i]; }
}

// ---------------- converters ----------------
__global__ void __launch_bounds__(256) conv_qk(
    const float* __restrict__ src, __nv_bfloat16* __restrict__ dst, float scale)
{
    __shared__ float t[32][65];
    int bh = blockIdx.y;
    int t0 = blockIdx.x * 64;
    const float* s = src + (size_t)bh * 32 * HW + t0;
    int tid = threadIdx.x;
    for (int e = tid; e < 2048; e += 256) {
        int d = e >> 6, tt = e & 63;
        t[d][tt] = s[(size_t)d * HW + tt] * scale;
    }
    __syncthreads();
    int j = tid >> 2, seg = (tid & 3) * 8;
    __nv_bfloat16 tmp[8];
#pragma unroll
    for (int i = 0; i < 8; i++) tmp[i] = __float2bfloat16(t[seg + i][j]);
    *(uint4*)(dst + ((size_t)bh * HW + t0 + j) * DK + seg) = *(uint4*)tmp;
}

__global__ void __launch_bounds__(256) conv_v()
{
    size_t i = ((size_t)blockIdx.x * 256 + threadIdx.x) * 4;
    float4 v = *(const float4*)(g_v + i);
    __nv_bfloat16 t[4];
    t[0] = __float2bfloat16(v.x); t[1] = __float2bfloat16(v.y);
    t[2] = __float2bfloat16(v.z); t[3] = __float2bfloat16(v.w);
    *(uint2*)(g_vh + i) = *(uint2*)t;
}

// ---------------- FA2-style flash TSA with mma.sync bf16 ----------------
#define QS_STR 40
#define VS_STR 136
__global__ void __launch_bounds__(256) flash_mma()
{
    __shared__ __nv_bfloat16 Qs[128 * QS_STR];
    __shared__ __nv_bfloat16 Ks[128 * QS_STR];
    __shared__ __nv_bfloat16 Vs[32 * VS_STR];
    int tid = threadIdx.x, wid = tid >> 5, lane = tid & 31;
    int bh = blockIdx.y, i0 = blockIdx.x * 128;
    int gr = lane >> 2, gc = (lane & 3) * 2;

    const __nv_bfloat16* qsrc = g_qh + ((size_t)bh * HW + i0) * DK;
    const __nv_bfloat16* ksrc = g_kh + (size_t)bh * HW * DK;
    const __nv_bfloat16* vsrc = g_vh + (size_t)bh * DK * HW;

    for (int e = tid; e < 512; e += 256) {
        int r = e >> 2, c8 = (e & 3) * 8;
        *(uint4*)(Qs + r * QS_STR + c8) = *(const uint4*)(qsrc + r * DK + c8);
    }
    __syncthreads();

    uint32_t qa[2][4];
    {
        const __nv_bfloat16* qb = Qs + (wid * 16 + gr) * QS_STR;
#pragma unroll
        for (int kc = 0; kc < 2; kc++) {
            qa[kc][0] = *(const uint32_t*)(qb + kc * 16 + gc);
            qa[kc][1] = *(const uint32_t*)(qb + 8 * QS_STR + kc * 16 + gc);
            qa[kc][2] = *(const uint32_t*)(qb + kc * 16 + gc + 8);
            qa[kc][3] = *(const uint32_t*)(qb + 8 * QS_STR + kc * 16 + gc + 8);
        }
    }

    float o[4][4];
#pragma unroll
    for (int i = 0; i < 4; i++)
#pragma unroll
        for (int j = 0; j < 4; j++) o[i][j] = 0.f;
    float l0 = 0.f, l1 = 0.f;

    for (int kt = 0; kt < 18; kt++) {
        int j0 = kt * 128;
        __syncthreads();
        for (int e = tid; e < 512; e += 256) {
            int r = e >> 2, c8 = (e & 3) * 8;
            *(uint4*)(Ks + r * QS_STR + c8) = *(const uint4*)(ksrc + (size_t)(j0 + r) * DK + c8);
        }
        for (int e = tid; e < 512; e += 256) {
            int d = e >> 4, c8 = (e & 15) * 8;
            *(uint4*)(Vs + d * VS_STR + c8) = *(const uint4*)(vsrc + (size_t)d * HW + j0 + c8);
        }
        __syncthreads();

        float s[16][4];
#pragma unroll
        for (int nt = 0; nt < 16; nt++) {
            s[nt][0] = 0.f; s[nt][1] = 0.f; s[nt][2] = 0.f; s[nt][3] = 0.f;
            const __nv_bfloat16* kb = Ks + (nt * 8 + gr) * QS_STR;
#pragma unroll
            for (int kc = 0; kc < 2; kc++) {
                uint32_t b0 = *(const uint32_t*)(kb + kc * 16 + gc);
                uint32_t b1 = *(const uint32_t*)(kb + kc * 16 + gc + 8);
                mma16816(s[nt], qa[kc], b0, b1);
            }
        }

        uint32_t pa_[8][4];
#pragma unroll
        for (int h2 = 0; h2 < 8; h2++) {
            float e00 = __expf(s[2 * h2][0]),     e01 = __expf(s[2 * h2][1]);
            float e02 = __expf(s[2 * h2][2]),     e03 = __expf(s[2 * h2][3]);
            float f00 = __expf(s[2 * h2 + 1][0]), f01 = __expf(s[2 * h2 + 1][1]);
            float f02 = __expf(s[2 * h2 + 1][2]), f03 = __expf(s[2 * h2 + 1][3]);
            l0 += (e00 + e01) + (f00 + f01);
            l1 += (e02 + e03) + (f02 + f03);
            pa_[h2][0] = pack_bf16x2(e01, e00);
            pa_[h2][1] = pack_bf16x2(e03, e02);
            pa_[h2][2] = pack_bf16x2(f01, f00);
            pa_[h2][3] = pack_bf16x2(f03, f02);
        }

#pragma unroll
        for (int kc2 = 0; kc2 < 8; kc2++) {
#pragma unroll
            for (int dt = 0; dt < 4; dt++) {
                const __nv_bfloat16* vb = Vs + (dt * 8 + gr) * VS_STR + kc2 * 16 + gc;
                uint32_t b0 = *(const uint32_t*)(vb);
                uint32_t b1 = *(const uint32_t*)(vb + 8);
                mma16816(o[dt], pa_[kc2], b0, b1);
            }
        }
    }

    l0 += __shfl_xor_sync(0xffffffffu, l0, 1);
    l0 += __shfl_xor_sync(0xffffffffu, l0, 2);
    l1 += __shfl_xor_sync(0xffffffffu, l1, 1);
    l1 += __shfl_xor_sync(0xffffffffu, l1, 2);
    float inv0 = 1.f / l0, inv1 = 1.f / l1;

    int b = bh >> 3, h = bh & 7;
    float* ob = g_tsa + ((size_t)b * CC + h * DK) * HW;
    int tok0 = i0 + wid * 16 + gr;
#pragma unroll
    for (int dt = 0; dt < 4; dt++) {
        int d = dt * 8 + gc;
        ob[(size_t)(d)     * HW + tok0]     = o[dt][0] * inv0;
        ob[(size_t)(d + 1) * HW + tok0]     = o[dt][1] * inv0;
        ob[(size_t)(d)     * HW + tok0 + 8] = o[dt][2] * inv1;
        ob[(size_t)(d + 1) * HW + tok0 + 8] = o[dt][3] * inv1;
    }
}

// ---------------- GSA raw scores (fp32) ----------------
__global__ void __launch_bounds__(256) pa_gemm()
{
    __shared__ float Ms[32][64];
    __shared__ float Ns[32][64];
    int b  = blockIdx.z;
    int i0 = blockIdx.x * 64;
    int j0 = blockIdx.y * 64;
    const float* mb_ = g_mn + (size_t)b * 64 * HW;
    const float* nb  = mb_ + (size_t)32 * HW;
    int tid = threadIdx.x;
    int tx = tid & 15, ty = tid >> 4;
    for (int e = tid; e < 2048; e += 256) {
        int c = e >> 6, i = e & 63;
        Ms[c][i] = mb_[(size_t)c * HW + i0 + i];
        Ns[c][i] = nb[(size_t)c * HW + j0 + i];
    }
    __syncthreads();
    float acc[4][4];
#pragma unroll
    for (int i = 0; i < 4; i++)
#pragma unroll
        for (int j = 0; j < 4; j++) acc[i][j] = 0.f;
#pragma unroll
    for (int c = 0; c < 32; c++) {
        float4 a  = *(float4*)&Ms[c][ty * 4];
        float4 nn = *(float4*)&Ns[c][tx * 4];
        float av[4] = {a.x, a.y, a.z, a.w};
        float nv[4] = {nn.x, nn.y, nn.z, nn.w};
#pragma unroll
        for (int i = 0; i < 4; i++)
#pragma unroll
            for (int j = 0; j < 4; j++)
                acc[i][j] = fmaf(av[i], nv[j], acc[i][j]);
    }
    float* pb = g_pa + (size_t)b * HW * HW;
#pragma unroll
    for (int i = 0; i < 4; i++) {
        float4 ov = make_float4(acc[i][0], acc[i][1], acc[i][2], acc[i][3]);
        *(float4*)(pb + (size_t)(i0 + ty * 4 + i) * HW + j0 + tx * 4) = ov;
    }
}

// ---------------- row softmax over pa (vectorized, 288 threads) -----------
__global__ void __launch_bounds__(288) softmax_rows()
{
    __shared__ float red[9];
    size_t row = blockIdx.x;
    float4* p4 = (float4*)(g_pa + row * HW);
    int tid = threadIdx.x;
    float4 v0 = p4[tid], v1 = p4[tid + 288];
    float mx = fmaxf(fmaxf(fmaxf(v0.x, v0.y), fmaxf(v0.z, v0.w)),
                     fmaxf(fmaxf(v1.x, v1.y), fmaxf(v1.z, v1.w)));
#pragma unroll
    for (int off = 16; off; off >>= 1)
        mx = fmaxf(mx, __shfl_xor_sync(0xffffffffu, mx, off));
    if ((tid & 31) == 0) red[tid >> 5] = mx;
    __syncthreads();
    float m9 = red[0];
#pragma unroll
    for (int i = 1; i < 9; i++) m9 = fmaxf(m9, red[i]);
    v0.x = fexp(v0.x - m9); v0.y = fexp(v0.y - m9);
    v0.z = fexp(v0.z - m9); v0.w = fexp(v0.w - m9);
    v1.x = fexp(v1.x - m9); v1.y = fexp(v1.y - m9);
    v1.z = fexp(v1.z - m9); v1.w = fexp(v1.w - m9);
    float s = (v0.x + v0.y) + (v0.z + v0.w) + (v1.x + v1.y) + (v1.z + v1.w);
#pragma unroll
    for (int off = 16; off; off >>= 1)
        s += __shfl_xor_sync(0xffffffffu, s, off);
    __syncthreads();
    if ((tid & 31) == 0) red[tid >> 5] = s;
    __syncthreads();
    float s9 = 0.f;
#pragma unroll
    for (int i = 0; i < 9; i++) s9 += red[i];
    float inv = 1.f / s9;
    v0.x *= inv; v0.y *= inv; v0.z *= inv; v0.w *= inv;
    v1.x *= inv; v1.y *= inv; v1.z *= inv; v1.w *= inv;
    p4[tid] = v0; p4[tid + 288] = v1;
}

// ---------------- launch ----------------
extern "C" void kernel_launch(void* const* d_in, const int* in_sizes, int n_in,
                              void* d_out, int out_size)
{
    const float* x   = (const float*)d_in[0];
    const float* wq  = (const float*)d_in[1];
    const float* bq  = (const float*)d_in[2];
    const float* wk  = (const float*)d_in[3];
    const float* bk  = (const float*)d_in[4];
    const float* wv  = (const float*)d_in[5];
    const float* bv  = (const float*)d_in[6];
    const float* wm  = (const float*)d_in[7];
    const float* bm  = (const float*)d_in[8];
    const float* wn  = (const float*)d_in[9];
    const float* bn  = (const float*)d_in[10];
    const float* ww  = (const float*)d_in[11];
    const float* bw  = (const float*)d_in[12];
    const float* wo  = (const float*)d_in[13];
    const float* bo  = (const float*)d_in[14];
    const float* gts = (const float*)d_in[15];
    const float* ggs = (const float*)d_in[16];
    float* out = (float*)d_out;

    float *pq, *pk, *pmn, *pwmn, *pbmn;
    __nv_bfloat16 *pqh, *pkh;
    cudaGetSymbolAddress((void**)&pq, g_q);
    cudaGetSymbolAddress((void**)&pk, g_k);
    cudaGetSymbolAddress((void**)&pmn, g_mn);
    cudaGetSymbolAddress((void**)&pwmn, g_wmn);
    cudaGetSymbolAddress((void**)&pbmn, g_bmn);
    cudaGetSymbolAddress((void**)&pqh, g_qh);
    cudaGetSymbolAddress((void**)&pkh, g_kh);

    static int smem_set = 0;
    const int DBUF_SMEM = (2 * ASZ + 2 * BSZ) * 4;   // 53248 B
    if (!smem_set) {
        cudaFuncSetAttribute(tf32_gsa, cudaFuncAttributeMaxDynamicSharedMemorySize, DBUF_SMEM);
        cudaFuncSetAttribute(tf32_final, cudaFuncAttributeMaxDynamicSharedMemorySize, DBUF_SMEM);
        smem_set = 1;
    }

    dim3 blk(256);

    concat_mn<<<32, blk>>>(wm, bm, wn, bn);

    tf32_proj4<<<dim3(36, 16), blk>>>(wq, bq, wk, bk, wv, bv, ww, bw, x);
    proj_gemm<<<dim3(BB * HW / 64, 1), blk>>>(pwmn, pbmn, x, pmn, 64);

    conv_qk<<<dim3(HW / 64, BB * HEADS), blk>>>(pq, pqh, 0.17677669529663687f);
    conv_qk<<<dim3(HW / 64, BB * HEADS), blk>>>(pk, pkh, 1.0f);
    conv_v<<<NCH / 1024, blk>>>();

    flash_mma<<<dim3(HW / 128, BB * HEADS), blk>>>();

    pa_gemm<<<dim3(HW / 64, HW / 64, BB), blk>>>();
    softmax_rows<<<BB * HW, dim3(288)>>>();
    tf32_gsa<<<dim3(36, 4), blk, DBUF_SMEM>>>();

    tf32_final<<<dim3(36, 4), blk, DBUF_SMEM>>>(wo, bo, x, gts, ggs, out);
}

// round 6
// speedup vs baseline: 3.1859x; 1.0459x over previous
#include <cuda_runtime.h>
#include <cuda_bf16.h>
#include <cstdint>

#define BB    2
#define CC    256
#define HW    2304
#define HEADS 8
#define DK    32
#define CR    32
#define NCH   (BB*CC*HW)

// ---------------- scratch (device globals; no allocation) ----------------
__device__ float g_w[NCH];              // wf projection (fp32)
__device__ float g_mn[BB*64*HW];        // m (rows 0-31) and n (rows 32-63)
__device__ float g_wmn[64*256];
__device__ float g_bmn[64];
__device__ float g_tsa[NCH];
__device__ float g_gsa[NCH];
__device__ float g_l[BB*HW];            // GSA softmax row sums
__device__ float g_pa[(size_t)BB*HW*HW]; // unnormalized exp(scores), 42.5 MB
__device__ __nv_bfloat16 g_qh[NCH];     // [bh][t][d], pre-scaled
__device__ __nv_bfloat16 g_kh[NCH];     // [bh][t][d]
__device__ __nv_bfloat16 g_vh[NCH];     // [bh][d][t]

// ---------------- mma helpers ----------------
__device__ __forceinline__ void mma16816(float* c, const uint32_t* a, uint32_t b0, uint32_t b1) {
    asm volatile(
        "mma.sync.aligned.m16n8k16.row.col.f32.bf16.bf16.f32 "
        "{%0,%1,%2,%3}, {%4,%5,%6,%7}, {%8,%9}, {%0,%1,%2,%3};"
        : "+f"(c[0]), "+f"(c[1]), "+f"(c[2]), "+f"(c[3])
        : "r"(a[0]), "r"(a[1]), "r"(a[2]), "r"(a[3]), "r"(b0), "r"(b1));
}
__device__ __forceinline__ void mma_tf32(float* c, const uint32_t* a, uint32_t b0, uint32_t b1) {
    asm volatile(
        "mma.sync.aligned.m16n8k8.row.col.f32.tf32.tf32.f32 "
        "{%0,%1,%2,%3}, {%4,%5,%6,%7}, {%8,%9}, {%0,%1,%2,%3};"
        : "+f"(c[0]), "+f"(c[1]), "+f"(c[2]), "+f"(c[3])
        : "r"(a[0]), "r"(a[1]), "r"(a[2]), "r"(a[3]), "r"(b0), "r"(b1));
}
__device__ __forceinline__ uint32_t pack_bf16x2(float hi, float lo) {
    uint32_t w;
    asm("cvt.rn.satfinite.bf16x2.f32 %0, %1, %2;" : "=r"(w) : "f"(hi), "f"(lo));
    return w;
}
__device__ __forceinline__ uint32_t cvt_tf32(float f) {
    uint32_t r;
    asm("cvt.rna.tf32.f32 %0, %1;" : "=r"(r) : "f"(f));
    return r;
}
__device__ __forceinline__ uint4 cvt4_tf32(float4 v) {
    uint4 o;
    o.x = cvt_tf32(v.x); o.y = cvt_tf32(v.y); o.z = cvt_tf32(v.z); o.w = cvt_tf32(v.w);
    return o;
}

#define AS_STR 36
#define BS_STR 136
#define ASZ (64 * AS_STR)
#define BSZ (32 * BS_STR)

__device__ __forceinline__ void tf32_chunk(
    const uint32_t* Ap, const uint32_t* Bp, float c[2][4][4],
    int warpm, int warpn, int gr, int gc)
{
#pragma unroll
    for (int ks = 0; ks < 4; ks++) {
        uint32_t a[2][4], bq[4][2];
#pragma unroll
        for (int mt = 0; mt < 2; mt++) {
            const uint32_t* ab = Ap + (warpm * 32 + mt * 16) * AS_STR + ks * 8 + gc;
            a[mt][0] = ab[gr * AS_STR];
            a[mt][1] = ab[(gr + 8) * AS_STR];
            a[mt][2] = ab[gr * AS_STR + 4];
            a[mt][3] = ab[(gr + 8) * AS_STR + 4];
        }
#pragma unroll
        for (int nt = 0; nt < 4; nt++) {
            const uint32_t* bb = Bp + (ks * 8 + gc) * BS_STR + warpn * 32 + nt * 8 + gr;
            bq[nt][0] = bb[0];
            bq[nt][1] = bb[4 * BS_STR];
        }
#pragma unroll
        for (int mt = 0; mt < 2; mt++)
#pragma unroll
            for (int nt = 0; nt < 4; nt++)
                mma_tf32(c[mt][nt], a[mt], bq[nt][0], bq[nt][1]);
    }
}

// ---------------- fused QKVW projection + bf16 layout epilogues -----------
// grid (36, 16), block 256. blockIdx.y>>2 selects q/k/v/w.
// q -> g_qh bf16 [bh][t][d] scaled; k -> g_kh bf16 [bh][t][d];
// v -> g_vh bf16 [bh][d][t]; w -> g_w fp32.
__global__ void __launch_bounds__(256) tf32_proj4(
    const float* __restrict__ wq, const float* __restrict__ bq,
    const float* __restrict__ wk, const float* __restrict__ bk,
    const float* __restrict__ wv, const float* __restrict__ bv,
    const float* __restrict__ ww, const float* __restrict__ bw,
    const float* __restrict__ x)
{
    __shared__ uint32_t As[ASZ];
    __shared__ uint32_t Bs[BSZ];
    int tid = threadIdx.x, lane = tid & 31, wid = tid >> 5;
    int gr = lane >> 2, gc = lane & 3;
    int sel  = blockIdx.y >> 2;
    int row0 = (blockIdx.y & 3) * 64;
    const float* W    = sel == 0 ? wq : sel == 1 ? wk : sel == 2 ? wv : ww;
    const float* bias = sel == 0 ? bq : sel == 1 ? bk : sel == 2 ? bv : bw;
    int b = blockIdx.x / 18, hw0 = (blockIdx.x % 18) * 128;
    const float* Bb = x + (size_t)b * CC * HW + hw0;
    int warpm = wid >> 2, warpn = wid & 3;
    float c[2][4][4];
#pragma unroll
    for (int i = 0; i < 2; i++)
#pragma unroll
        for (int j = 0; j < 4; j++)
#pragma unroll
            for (int k = 0; k < 4; k++) c[i][j][k] = 0.f;

    for (int k0 = 0; k0 < 256; k0 += 32) {
#pragma unroll
        for (int i = 0; i < 2; i++) {
            int e = tid + i * 256;
            int r = e >> 3, k4 = (e & 7) * 4;
            float4 w4 = *(const float4*)(W + (size_t)(row0 + r) * 256 + k0 + k4);
            *(uint4*)(As + r * AS_STR + k4) = cvt4_tf32(w4);
        }
#pragma unroll
        for (int i = 0; i < 4; i++) {
            int e = tid + i * 256;
            int k = e >> 5, n4 = (e & 31) * 4;
            float4 v4 = *(const float4*)(Bb + (size_t)(k0 + k) * HW + n4);
            *(uint4*)(Bs + k * BS_STR + n4) = cvt4_tf32(v4);
        }
        __syncthreads();
        tf32_chunk(As, Bs, c, warpm, warpn, gr, gc);
        __syncthreads();
    }

    if (sel == 3) {                       // wf: fp32, [b][c][t]
#pragma unroll
        for (int mt = 0; mt < 2; mt++)
#pragma unroll
            for (int rh = 0; rh < 2; rh++) {
                int r = row0 + warpm * 32 + mt * 16 + rh * 8 + gr;
                float bv2 = bias[r];
#pragma unroll
                for (int nt = 0; nt < 4; nt++) {
                    int col = hw0 + warpn * 32 + nt * 8 + gc * 2;
                    size_t idx = (size_t)b * CC * HW + (size_t)r * HW + col;
                    *(float2*)(g_w + idx) = make_float2(c[mt][nt][rh * 2 + 0] + bv2,
                                                        c[mt][nt][rh * 2 + 1] + bv2);
                }
            }
    } else if (sel == 2) {                // v: bf16 packed, [bh][d][t] == [b][r][t]
#pragma unroll
        for (int mt = 0; mt < 2; mt++)
#pragma unroll
            for (int rh = 0; rh < 2; rh++) {
                int r = row0 + warpm * 32 + mt * 16 + rh * 8 + gr;
                float bv2 = bias[r];
#pragma unroll
                for (int nt = 0; nt < 4; nt++) {
                    int col = hw0 + warpn * 32 + nt * 8 + gc * 2;
                    size_t idx = (size_t)(b * 256 + r) * HW + col;
                    uint32_t pw = pack_bf16x2(c[mt][nt][rh * 2 + 1] + bv2,
                                              c[mt][nt][rh * 2 + 0] + bv2);
                    *(uint32_t*)(g_vh + idx) = pw;
                }
            }
    } else {                              // q/k: bf16 scatter into [bh][t][d]
        float scale = sel == 0 ? 0.17677669529663687f : 1.0f;
        __nv_bfloat16* dst = sel == 0 ? g_qh : g_kh;
#pragma unroll
        for (int mt = 0; mt < 2; mt++)
#pragma unroll
            for (int rh = 0; rh < 2; rh++) {
                int r = row0 + warpm * 32 + mt * 16 + rh * 8 + gr;
                float bv2 = bias[r];
                size_t hb = (size_t)(b * 8 + (r >> 5)) * HW;
                int d = r & 31;
#pragma unroll
                for (int nt = 0; nt < 4; nt++) {
                    int col = hw0 + warpn * 32 + nt * 8 + gc * 2;
                    float v0 = (c[mt][nt][rh * 2 + 0] + bv2) * scale;
                    float v1 = (c[mt][nt][rh * 2 + 1] + bv2) * scale;
                    dst[(hb + col)     * 32 + d] = __float2bfloat16(v0);
                    dst[(hb + col + 1) * 32 + d] = __float2bfloat16(v1);
                }
            }
    }
}

// ---------------- fused GSA scores + exp (split-tf32, fp32-accurate) ------
// grid (72, BB), block 256. Each CTA: 32 pa rows x full 2304 cols.
// Writes pa = exp(s) (unnormalized) and g_l row sums.
#define PAB_STR 68
__global__ void __launch_bounds__(256) pa_softmax()
{
    __shared__ uint32_t Ahi[32 * 36], Alo[32 * 36];
    __shared__ uint32_t Bhi[32 * PAB_STR], Blo[32 * PAB_STR];
    __shared__ float red[32 * 8];
    int tid = threadIdx.x, lane = tid & 31, wid = tid >> 5;
    int gr = lane >> 2, gc = lane & 3;
    int b = blockIdx.y, n0 = blockIdx.x * 32;
    const float* Mp = g_mn + (size_t)b * 64 * HW;        // m-proj: ch 0..31
    const float* Np = Mp + (size_t)32 * HW;              // n-proj

    // A fill + transpose + hi/lo split: Ahi/Alo[n][ch]
    for (int e = tid; e < 1024; e += 256) {
        int ch = e >> 5, n = e & 31;
        float v = Mp[(size_t)ch * HW + n0 + n];
        uint32_t h = cvt_tf32(v);
        Ahi[n * 36 + ch] = h;
        Alo[n * 36 + ch] = cvt_tf32(v - __uint_as_float(h));
    }

    int bm = tid & 63, bc0 = tid >> 6;     // B fill: ch = bc0 + i*4, m = bm
    float rbv[8];
#pragma unroll
    for (int i = 0; i < 8; i++)
        rbv[i] = Np[(size_t)(bc0 + i * 4) * HW + bm];

    float rs[2][2] = {{0.f, 0.f}, {0.f, 0.f}};
    float* pab = g_pa + (size_t)b * HW * HW;
    __syncthreads();

    for (int t = 0; t < 36; t++) {
#pragma unroll
        for (int i = 0; i < 8; i++) {
            int ch = bc0 + i * 4;
            uint32_t h = cvt_tf32(rbv[i]);
            Bhi[ch * PAB_STR + bm] = h;
            Blo[ch * PAB_STR + bm] = cvt_tf32(rbv[i] - __uint_as_float(h));
        }
        __syncthreads();
        if (t + 1 < 36) {
#pragma unroll
            for (int i = 0; i < 8; i++)
                rbv[i] = Np[(size_t)(bc0 + i * 4) * HW + (t + 1) * 64 + bm];
        }
        float c[2][4];
#pragma unroll
        for (int mt = 0; mt < 2; mt++)
#pragma unroll
            for (int j = 0; j < 4; j++) c[mt][j] = 0.f;
#pragma unroll
        for (int ks = 0; ks < 4; ks++) {
            uint32_t ah[2][4], al[2][4];
#pragma unroll
            for (int mt = 0; mt < 2; mt++) {
                int rb = mt * 16;
                ah[mt][0] = Ahi[(rb + gr) * 36 + ks * 8 + gc];
                ah[mt][1] = Ahi[(rb + gr + 8) * 36 + ks * 8 + gc];
                ah[mt][2] = Ahi[(rb + gr) * 36 + ks * 8 + gc + 4];
                ah[mt][3] = Ahi[(rb + gr + 8) * 36 + ks * 8 + gc + 4];
                al[mt][0] = Alo[(rb + gr) * 36 + ks * 8 + gc];
                al[mt][1] = Alo[(rb + gr + 8) * 36 + ks * 8 + gc];
                al[mt][2] = Alo[(rb + gr) * 36 + ks * 8 + gc + 4];
                al[mt][3] = Alo[(rb + gr + 8) * 36 + ks * 8 + gc + 4];
            }
            int colb = wid * 8 + gr;
            uint32_t bh0 = Bhi[(ks * 8 + gc) * PAB_STR + colb];
            uint32_t bh1 = Bhi[(ks * 8 + gc + 4) * PAB_STR + colb];
            uint32_t bl0 = Blo[(ks * 8 + gc) * PAB_STR + colb];
            uint32_t bl1 = Blo[(ks * 8 + gc + 4) * PAB_STR + colb];
#pragma unroll
            for (int mt = 0; mt < 2; mt++) {
                mma_tf32(c[mt], ah[mt], bh0, bh1);
                mma_tf32(c[mt], ah[mt], bl0, bl1);
                mma_tf32(c[mt], al[mt], bh0, bh1);
            }
        }
        int m_base = t * 64 + wid * 8 + gc * 2;
#pragma unroll
        for (int mt = 0; mt < 2; mt++)
#pragma unroll
            for (int rh = 0; rh < 2; rh++) {
                float p0 = __expf(c[mt][rh * 2 + 0]);
                float p1 = __expf(c[mt][rh * 2 + 1]);
                rs[mt][rh] += p0 + p1;
                int n = n0 + mt * 16 + rh * 8 + gr;
                *(float2*)(pab + (size_t)n * HW + m_base) = make_float2(p0, p1);
            }
        __syncthreads();
    }

#pragma unroll
    for (int mt = 0; mt < 2; mt++)
#pragma unroll
        for (int rh = 0; rh < 2; rh++) {
            float v = rs[mt][rh];
            v += __shfl_xor_sync(0xffffffffu, v, 1);
            v += __shfl_xor_sync(0xffffffffu, v, 2);
            if (gc == 0) red[(mt * 16 + rh * 8 + gr) * 8 + wid] = v;
        }
    __syncthreads();
    if (tid < 32) {
        float s = 0.f;
#pragma unroll
        for (int w = 0; w < 8; w++) s += red[tid * 8 + w];
        g_l[(size_t)b * HW + n0 + tid] = s;
    }
}

// ---------------- double-buffered tf32 GSA: gsa = (wf @ pa^T) / l ---------
__global__ void __launch_bounds__(256) tf32_gsa()
{
    extern __shared__ uint32_t dsm[];
    uint32_t* As = dsm;
    uint32_t* Bs = dsm + 2 * ASZ;
    int tid = threadIdx.x, lane = tid & 31, wid = tid >> 5;
    int gr = lane >> 2, gc = lane & 3;
    int c0 = blockIdx.y * 64;
    int b = blockIdx.x / 18, n0 = (blockIdx.x % 18) * 128;
    const float* wfb = g_w + (size_t)b * CC * HW;
    const float* pab = g_pa + (size_t)b * HW * HW;
    int warpm = wid >> 2, warpn = wid & 3;

    int ar = tid >> 3, ak4 = (tid & 7) * 4;
    int ar2 = (tid + 256) >> 3;
    int bn = tid & 127, bk4_0 = (tid >> 7) * 4;

    float4 ra[2], rb[4];
#pragma unroll
    for (int i = 0; i < 2; i++) {
        int r = (i == 0) ? ar : ar2;
        ra[i] = *(const float4*)(wfb + (size_t)(c0 + r) * HW + 0 + ak4);
    }
#pragma unroll
    for (int i = 0; i < 4; i++)
        rb[i] = *(const float4*)(pab + (size_t)(n0 + bn) * HW + 0 + (bk4_0 + i * 8));
#pragma unroll
    for (int i = 0; i < 2; i++) {
        int r = (i == 0) ? ar : ar2;
        *(uint4*)(As + r * AS_STR + ak4) = cvt4_tf32(ra[i]);
    }
#pragma unroll
    for (int i = 0; i < 4; i++) {
        int k4 = bk4_0 + i * 8;
        Bs[(k4 + 0) * BS_STR + bn] = cvt_tf32(rb[i].x);
        Bs[(k4 + 1) * BS_STR + bn] = cvt_tf32(rb[i].y);
        Bs[(k4 + 2) * BS_STR + bn] = cvt_tf32(rb[i].z);
        Bs[(k4 + 3) * BS_STR + bn] = cvt_tf32(rb[i].w);
    }
    __syncthreads();

    float c[2][4][4];
#pragma unroll
    for (int i = 0; i < 2; i++)
#pragma unroll
        for (int j = 0; j < 4; j++)
#pragma unroll
            for (int k = 0; k < 4; k++) c[i][j][k] = 0.f;

    for (int it = 0; it < 72; it++) {
        int p = it & 1;
        int m1 = (it + 1) * 32;
        if (it + 1 < 72) {
#pragma unroll
            for (int i = 0; i < 2; i++) {
                int r = (i == 0) ? ar : ar2;
                ra[i] = *(const float4*)(wfb + (size_t)(c0 + r) * HW + m1 + ak4);
            }
#pragma unroll
            for (int i = 0; i < 4; i++)
                rb[i] = *(const float4*)(pab + (size_t)(n0 + bn) * HW + m1 + (bk4_0 + i * 8));
        }
        tf32_chunk(As + p * ASZ, Bs + p * BSZ, c, warpm, warpn, gr, gc);
        if (it + 1 < 72) {
            uint32_t* Ad = As + (p ^ 1) * ASZ;
            uint32_t* Bd = Bs + (p ^ 1) * BSZ;
#pragma unroll
            for (int i = 0; i < 2; i++) {
                int r = (i == 0) ? ar : ar2;
                *(uint4*)(Ad + r * AS_STR + ak4) = cvt4_tf32(ra[i]);
            }
#pragma unroll
            for (int i = 0; i < 4; i++) {
                int k4 = bk4_0 + i * 8;
                Bd[(k4 + 0) * BS_STR + bn] = cvt_tf32(rb[i].x);
                Bd[(k4 + 1) * BS_STR + bn] = cvt_tf32(rb[i].y);
                Bd[(k4 + 2) * BS_STR + bn] = cvt_tf32(rb[i].z);
                Bd[(k4 + 3) * BS_STR + bn] = cvt_tf32(rb[i].w);
            }
        }
        __syncthreads();
    }

    // column-wise normalization by row sums l[n]
    float inv[4][2];
#pragma unroll
    for (int nt = 0; nt < 4; nt++) {
        int col = n0 + warpn * 32 + nt * 8 + gc * 2;
        inv[nt][0] = 1.f / g_l[(size_t)b * HW + col];
        inv[nt][1] = 1.f / g_l[(size_t)b * HW + col + 1];
    }
    float* ob = g_gsa + (size_t)b * CC * HW;
#pragma unroll
    for (int mt = 0; mt < 2; mt++)
#pragma unroll
        for (int rh = 0; rh < 2; rh++) {
            int r = c0 + warpm * 32 + mt * 16 + rh * 8 + gr;
#pragma unroll
            for (int nt = 0; nt < 4; nt++) {
                int col = n0 + warpn * 32 + nt * 8 + gc * 2;
                *(float2*)(ob + (size_t)r * HW + col) =
                    make_float2(c[mt][nt][rh * 2 + 0] * inv[nt][0],
                                c[mt][nt][rh * 2 + 1] * inv[nt][1]);
            }
        }
}

// ---------------- double-buffered final GEMM + fusion epilogue ------------
__global__ void __launch_bounds__(256) tf32_final(
    const float* __restrict__ wo, const float* __restrict__ bo,
    const float* __restrict__ xin,
    const float* __restrict__ gt_p, const float* __restrict__ gg_p,
    float* __restrict__ out)
{
    extern __shared__ uint32_t dsm[];
    uint32_t* As = dsm;
    uint32_t* Bs = dsm + 2 * ASZ;
    int tid = threadIdx.x, lane = tid & 31, wid = tid >> 5;
    int gr = lane >> 2, gc = lane & 3;
    int row0 = blockIdx.y * 64;
    int b = blockIdx.x / 18, hw0 = (blockIdx.x % 18) * 128;
    const float* Bb = g_gsa + (size_t)b * CC * HW + hw0;
    int warpm = wid >> 2, warpn = wid & 3;

    int ar = tid >> 3, ak4 = (tid & 7) * 4;
    int ar2 = (tid + 256) >> 3;
    int bk = tid >> 5, bn4 = (tid & 31) * 4;

    float4 ra[2], rb[4];
#pragma unroll
    for (int i = 0; i < 2; i++) {
        int r = (i == 0) ? ar : ar2;
        ra[i] = *(const float4*)(wo + (size_t)(row0 + r) * 256 + 0 + ak4);
    }
#pragma unroll
    for (int i = 0; i < 4; i++)
        rb[i] = *(const float4*)(Bb + (size_t)(0 + bk + i * 8) * HW + bn4);
#pragma unroll
    for (int i = 0; i < 2; i++) {
        int r = (i == 0) ? ar : ar2;
        *(uint4*)(As + r * AS_STR + ak4) = cvt4_tf32(ra[i]);
    }
#pragma unroll
    for (int i = 0; i < 4; i++)
        *(uint4*)(Bs + (bk + i * 8) * BS_STR + bn4) = cvt4_tf32(rb[i]);
    __syncthreads();

    float c[2][4][4];
#pragma unroll
    for (int i = 0; i < 2; i++)
#pragma unroll
        for (int j = 0; j < 4; j++)
#pragma unroll
            for (int k = 0; k < 4; k++) c[i][j][k] = 0.f;

    for (int it = 0; it < 8; it++) {
        int p = it & 1;
        int k1 = (it + 1) * 32;
        if (it + 1 < 8) {
#pragma unroll
            for (int i = 0; i < 2; i++) {
                int r = (i == 0) ? ar : ar2;
                ra[i] = *(const float4*)(wo + (size_t)(row0 + r) * 256 + k1 + ak4);
            }
#pragma unroll
            for (int i = 0; i < 4; i++)
                rb[i] = *(const float4*)(Bb + (size_t)(k1 + bk + i * 8) * HW + bn4);
        }
        tf32_chunk(As + p * ASZ, Bs + p * BSZ, c, warpm, warpn, gr, gc);
        if (it + 1 < 8) {
            uint32_t* Ad = As + (p ^ 1) * ASZ;
            uint32_t* Bd = Bs + (p ^ 1) * BSZ;
#pragma unroll
            for (int i = 0; i < 2; i++) {
                int r = (i == 0) ? ar : ar2;
                *(uint4*)(Ad + r * AS_STR + ak4) = cvt4_tf32(ra[i]);
            }
#pragma unroll
            for (int i = 0; i < 4; i++)
                *(uint4*)(Bd + (bk + i * 8) * BS_STR + bn4) = cvt4_tf32(rb[i]);
        }
        __syncthreads();
    }

    float gt = gt_p[0], gg = gg_p[0];
#pragma unroll
    for (int mt = 0; mt < 2; mt++)
#pragma unroll
        for (int rh = 0; rh < 2; rh++) {
            int r = row0 + warpm * 32 + mt * 16 + rh * 8 + gr;
            float bv = bo[r];
#pragma unroll
            for (int nt = 0; nt < 4; nt++) {
                int col = hw0 + warpn * 32 + nt * 8 + gc * 2;
                size_t idx = (size_t)b * CC * HW + (size_t)r * HW + col;
                float2 x2 = *(const float2*)(xin + idx);
                float2 t2 = *(const float2*)(g_tsa + idx);
                float2 o2;
                o2.x = gt * t2.x + gg * (c[mt][nt][rh * 2 + 0] + bv) + x2.x;
                o2.y = gt * t2.y + gg * (c[mt][nt][rh * 2 + 1] + bv) + x2.y;
                *(float2*)(out + idx) = o2;
            }
        }
}

// ---------------- fp32 proj (m/n, concentration-sensitive) ----------------
__global__ void __launch_bounds__(256) proj_gemm(
    const float* __restrict__ W, const float* __restrict__ bias,
    const float* __restrict__ x, float* __restrict__ out, int Co)
{
    __shared__ float As[16][64];
    __shared__ float Bs[16][64];
    int jt  = blockIdx.x;
    int o0  = blockIdx.y * 64;
    int b   = (jt * 64) / HW;
    int hw0 = (jt * 64) % HW;
    const float* xb = x + (size_t)b * CC * HW + hw0;
    int tid = threadIdx.x;
    int tx = tid & 15, ty = tid >> 4;
    float acc[4][4];
#pragma unroll
    for (int i = 0; i < 4; i++)
#pragma unroll
        for (int j = 0; j < 4; j++) acc[i][j] = 0.f;

    int lo  = tid >> 2;
    int lk4 = (tid & 3) * 4;
    int bk  = tid >> 4;
    int bj4 = (tid & 15) * 4;

    for (int k0 = 0; k0 < CC; k0 += 16) {
        float4 wv = make_float4(0.f, 0.f, 0.f, 0.f);
        if (o0 + lo < Co)
            wv = *(const float4*)(W + (size_t)(o0 + lo) * CC + k0 + lk4);
        As[lk4 + 0][lo] = wv.x; As[lk4 + 1][lo] = wv.y;
        As[lk4 + 2][lo] = wv.z; As[lk4 + 3][lo] = wv.w;
        float4 xv = *(const float4*)(xb + (size_t)(k0 + bk) * HW + bj4);
        *(float4*)&Bs[bk][bj4] = xv;
        __syncthreads();
#pragma unroll
        for (int k = 0; k < 16; k++) {
            float4 a  = *(float4*)&As[k][ty * 4];
            float4 bb = *(float4*)&Bs[k][tx * 4];
            float av[4] = {a.x, a.y, a.z, a.w};
            float bv[4] = {bb.x, bb.y, bb.z, bb.w};
#pragma unroll
            for (int i = 0; i < 4; i++)
#pragma unroll
                for (int j = 0; j < 4; j++)
                    acc[i][j] = fmaf(av[i], bv[j], acc[i][j]);
        }
        __syncthreads();
    }
#pragma unroll
    for (int i = 0; i < 4; i++) {
        int o = o0 + ty * 4 + i;
        if (o < Co) {
            float bsv = bias[o];
            float4 ov = make_float4(acc[i][0] + bsv, acc[i][1] + bsv,
                                    acc[i][2] + bsv, acc[i][3] + bsv);
            *(float4*)(out + (size_t)b * Co * HW + (size_t)o * HW + hw0 + tx * 4) = ov;
        }
    }
}

__global__ void __launch_bounds__(256) concat_mn(
    const float* __restrict__ wm, const float* __restrict__ bm,
    const float* __restrict__ wn, const float* __restrict__ bn)
{
    int i = blockIdx.x * 256 + threadIdx.x;
    if (i < 32 * 256) { g_wmn[i] = wm[i]; g_wmn[32 * 256 + i] = wn[i]; }
    if (i < 32) { g_bmn[i] = bm[i]; g_bmn[32 + i] = bn[i]; }
}

// ---------------- FA2-style flash TSA with mma.sync bf16 ----------------
#define QS_STR 40
#define VS_STR 136
__global__ void __launch_bounds__(256) flash_mma()
{
    __shared__ __nv_bfloat16 Qs[128 * QS_STR];
    __shared__ __nv_bfloat16 Ks[128 * QS_STR];
    __shared__ __nv_bfloat16 Vs[32 * VS_STR];
    int tid = threadIdx.x, wid = tid >> 5, lane = tid & 31;
    int bh = blockIdx.y, i0 = blockIdx.x * 128;
    int gr = lane >> 2, gc = (lane & 3) * 2;

    const __nv_bfloat16* qsrc = g_qh + ((size_t)bh * HW + i0) * DK;
    const __nv_bfloat16* ksrc = g_kh + (size_t)bh * HW * DK;
    const __nv_bfloat16* vsrc = g_vh + (size_t)bh * DK * HW;

    for (int e = tid; e < 512; e += 256) {
        int r = e >> 2, c8 = (e & 3) * 8;
        *(uint4*)(Qs + r * QS_STR + c8) = *(const uint4*)(qsrc + r * DK + c8);
    }
    __syncthreads();

    uint32_t qa[2][4];
    {
        const __nv_bfloat16* qb = Qs + (wid * 16 + gr) * QS_STR;
#pragma unroll
        for (int kc = 0; kc < 2; kc++) {
            qa[kc][0] = *(const uint32_t*)(qb + kc * 16 + gc);
            qa[kc][1] = *(const uint32_t*)(qb + 8 * QS_STR + kc * 16 + gc);
            qa[kc][2] = *(const uint32_t*)(qb + kc * 16 + gc + 8);
            qa[kc][3] = *(const uint32_t*)(qb + 8 * QS_STR + kc * 16 + gc + 8);
        }
    }

    float o[4][4];
#pragma unroll
    for (int i = 0; i < 4; i++)
#pragma unroll
        for (int j = 0; j < 4; j++) o[i][j] = 0.f;
    float l0 = 0.f, l1 = 0.f;

    for (int kt = 0; kt < 18; kt++) {
        int j0 = kt * 128;
        __syncthreads();
        for (int e = tid; e < 512; e += 256) {
            int r = e >> 2, c8 = (e & 3) * 8;
            *(uint4*)(Ks + r * QS_STR + c8) = *(const uint4*)(ksrc + (size_t)(j0 + r) * DK + c8);
        }
        for (int e = tid; e < 512; e += 256) {
            int d = e >> 4, c8 = (e & 15) * 8;
            *(uint4*)(Vs + d * VS_STR + c8) = *(const uint4*)(vsrc + (size_t)d * HW + j0 + c8);
        }
        __syncthreads();

        float s[16][4];
#pragma unroll
        for (int nt = 0; nt < 16; nt++) {
            s[nt][0] = 0.f; s[nt][1] = 0.f; s[nt][2] = 0.f; s[nt][3] = 0.f;
            const __nv_bfloat16* kb = Ks + (nt * 8 + gr) * QS_STR;
#pragma unroll
            for (int kc = 0; kc < 2; kc++) {
                uint32_t b0 = *(const uint32_t*)(kb + kc * 16 + gc);
                uint32_t b1 = *(const uint32_t*)(kb + kc * 16 + gc + 8);
                mma16816(s[nt], qa[kc], b0, b1);
            }
        }

        uint32_t pa_[8][4];
#pragma unroll
        for (int h2 = 0; h2 < 8; h2++) {
            float e00 = __expf(s[2 * h2][0]),     e01 = __expf(s[2 * h2][1]);
            float e02 = __expf(s[2 * h2][2]),     e03 = __expf(s[2 * h2][3]);
            float f00 = __expf(s[2 * h2 + 1][0]), f01 = __expf(s[2 * h2 + 1][1]);
            float f02 = __expf(s[2 * h2 + 1][2]), f03 = __expf(s[2 * h2 + 1][3]);
            l0 += (e00 + e01) + (f00 + f01);
            l1 += (e02 + e03) + (f02 + f03);
            pa_[h2][0] = pack_bf16x2(e01, e00);
            pa_[h2][1] = pack_bf16x2(e03, e02);
            pa_[h2][2] = pack_bf16x2(f01, f00);
            pa_[h2][3] = pack_bf16x2(f03, f02);
        }

#pragma unroll
        for (int kc2 = 0; kc2 < 8; kc2++) {
#pragma unroll
            for (int dt = 0; dt < 4; dt++) {
                const __nv_bfloat16* vb = Vs + (dt * 8 + gr) * VS_STR + kc2 * 16 + gc;
                uint32_t b0 = *(const uint32_t*)(vb);
                uint32_t b1 = *(const uint32_t*)(vb + 8);
                mma16816(o[dt], pa_[kc2], b0, b1);
            }
        }
    }

    l0 += __shfl_xor_sync(0xffffffffu, l0, 1);
    l0 += __shfl_xor_sync(0xffffffffu, l0, 2);
    l1 += __shfl_xor_sync(0xffffffffu, l1, 1);
    l1 += __shfl_xor_sync(0xffffffffu, l1, 2);
    float inv0 = 1.f / l0, inv1 = 1.f / l1;

    int b = bh >> 3, h = bh & 7;
    float* ob = g_tsa + ((size_t)b * CC + h * DK) * HW;
    int tok0 = i0 + wid * 16 + gr;
#pragma unroll
    for (int dt = 0; dt < 4; dt++) {
        int d = dt * 8 + gc;
        ob[(size_t)(d)     * HW + tok0]     = o[dt][0] * inv0;
        ob[(size_t)(d + 1) * HW + tok0]     = o[dt][1] * inv0;
        ob[(size_t)(d)     * HW + tok0 + 8] = o[dt][2] * inv1;
        ob[(size_t)(d + 1) * HW + tok0 + 8] = o[dt][3] * inv1;
    }
}

// ---------------- launch ----------------
extern "C" void kernel_launch(void* const* d_in, const int* in_sizes, int n_in,
                              void* d_out, int out_size)
{
    const float* x   = (const float*)d_in[0];
    const float* wq  = (const float*)d_in[1];
    const float* bq  = (const float*)d_in[2];
    const float* wk  = (const float*)d_in[3];
    const float* bk  = (const float*)d_in[4];
    const float* wv  = (const float*)d_in[5];
    const float* bv  = (const float*)d_in[6];
    const float* wm  = (const float*)d_in[7];
    const float* bm  = (const float*)d_in[8];
    const float* wn  = (const float*)d_in[9];
    const float* bn  = (const float*)d_in[10];
    const float* ww  = (const float*)d_in[11];
    const float* bw  = (const float*)d_in[12];
    const float* wo  = (const float*)d_in[13];
    const float* bo  = (const float*)d_in[14];
    const float* gts = (const float*)d_in[15];
    const float* ggs = (const float*)d_in[16];
    float* out = (float*)d_out;

    float *pmn, *pwmn, *pbmn;
    cudaGetSymbolAddress((void**)&pmn, g_mn);
    cudaGetSymbolAddress((void**)&pwmn, g_wmn);
    cudaGetSymbolAddress((void**)&pbmn, g_bmn);

    static int smem_set = 0;
    const int DBUF_SMEM = (2 * ASZ + 2 * BSZ) * 4;   // 53248 B
    if (!smem_set) {
        cudaFuncSetAttribute(tf32_gsa, cudaFuncAttributeMaxDynamicSharedMemorySize, DBUF_SMEM);
        cudaFuncSetAttribute(tf32_final, cudaFuncAttributeMaxDynamicSharedMemorySize, DBUF_SMEM);
        smem_set = 1;
    }

    dim3 blk(256);

    concat_mn<<<32, blk>>>(wm, bm, wn, bn);

    tf32_proj4<<<dim3(36, 16), blk>>>(wq, bq, wk, bk, wv, bv, ww, bw, x);
    proj_gemm<<<dim3(BB * HW / 64, 1), blk>>>(pwmn, pbmn, x, pmn, 64);

    flash_mma<<<dim3(HW / 128, BB * HEADS), blk>>>();

    pa_softmax<<<dim3(HW / 32, BB), blk>>>();
    tf32_gsa<<<dim3(36, 4), blk, DBUF_SMEM>>>();

    tf32_final<<<dim3(36, 4), blk, DBUF_SMEM>>>(wo, bo, x, gts, ggs, out);
}